// round 9
// baseline (speedup 1.0000x reference)
#include <cuda_runtime.h>
#include <cuda_bf16.h>
#include <cstdint>

// ---------------- problem constants ----------------
#define D_    64
#define HW_   4096
#define K_    512
#define NPTS  131072
#define NELEM 8388608LL

#define MTPB   512
#define MGRID  148
#define NTILES (NPTS / 128)   // 1024

// ---- smem byte offsets (A/B tiles 1024-aligned for SW128) ----
#define SM_Y     0        // 512 f32
#define SM_BKF   2048     // 128 int
#define SM_FLAG  2560     // 128 int
#define SM_RED   3072     // 16 f32
#define SM_M1    3136     // 128*2 f32
#define SM_M2    4160     // 128*2 f32
#define SM_K1    5184     // 128*2 int
#define SM_PAL   6208     // 4*128 f32 (per (q4,p) partial ||al||^2)
#define SM_PAH   8256     // 4*128 f32 (per (q4,p) partial ||ah||^2)
#define SM_BMAX  10304    // 2 f32 (Bh, Bl)
#define SM_AHI   11264    // 128 rows * 128 B  bf16 z-hi  (SW128)
#define SM_BH    27648    // 512 rows * 128 B  bf16 cb-hi (SW128)
#define SMEM_TOTAL 93184  // ~91 KB

// ---------------- device globals (zero-init; finalize resets) ----------------
__device__ double g_loss_accum;
__device__ int    g_flag_count;
__device__ int    g_worklist[NPTS];
__device__ float  g_y[K_];

#define SWZ128(off) ((off) ^ (((off) >> 3) & 0x70))

__device__ __forceinline__ uint32_t smem_u32_of(const void* p) {
    uint32_t a;
    asm("{ .reg .u64 t; cvta.to.shared.u64 t, %1; cvt.u32.u64 %0, t; }"
        : "=r"(a) : "l"(p));
    return a;
}
__device__ __forceinline__ void mma_bf16(float* c, const uint32_t* a,
                                         uint32_t b0, uint32_t b1) {
    asm volatile(
        "mma.sync.aligned.m16n8k16.row.col.f32.bf16.bf16.f32 "
        "{%0,%1,%2,%3}, {%4,%5,%6,%7}, {%8,%9}, {%0,%1,%2,%3};"
        : "+f"(c[0]), "+f"(c[1]), "+f"(c[2]), "+f"(c[3])
        : "r"(a[0]), "r"(a[1]), "r"(a[2]), "r"(a[3]), "r"(b0), "r"(b1));
}
__device__ __forceinline__ void ldsm_x4(uint32_t* r, uint32_t addr) {
    asm volatile(
        "ldmatrix.sync.aligned.m8n8.x4.shared.b16 {%0,%1,%2,%3}, [%4];"
        : "=r"(r[0]), "=r"(r[1]), "=r"(r[2]), "=r"(r[3]) : "r"(addr));
}
__device__ __forceinline__ uint32_t pack_bf16x2(float lo, float hi) {
    uint32_t u;
    asm("cvt.rn.bf16x2.f32 %0, %1, %2;" : "=r"(u) : "f"(hi), "f"(lo));
    return u;
}
// Merge candidate sets {(m1,k1), m2} U {(om1,ok1), om2}; ties -> smaller index.
__device__ __forceinline__ void merge3(float& m1, int& k1, float& m2,
                                       float om1, int ok1, float om2) {
    if (om1 < m1 || (om1 == m1 && ok1 < k1)) {
        m2 = fminf(m1, om2);
        m1 = om1; k1 = ok1;
    } else {
        m2 = fminf(m2, om1);
    }
}

// ---------------- main: persistent, single-pass bf16 screen ----------------
__global__ __launch_bounds__(MTPB, 1)
void vq_main_kernel(const float* __restrict__ z,
                    const float* __restrict__ cb,
                    float* __restrict__ out) {
    extern __shared__ char smem[];
    const uint32_t smb = smem_u32_of(smem);
    float* s_y    = (float*)(smem + SM_Y);
    int*   s_bkf  = (int*)(smem + SM_BKF);
    int*   s_flag = (int*)(smem + SM_FLAG);
    float* s_red  = (float*)(smem + SM_RED);
    float* s_m1   = (float*)(smem + SM_M1);
    float* s_m2   = (float*)(smem + SM_M2);
    int*   s_k1   = (int*)(smem + SM_K1);
    float* s_pal  = (float*)(smem + SM_PAL);
    float* s_pah  = (float*)(smem + SM_PAH);
    float* s_bmax = (float*)(smem + SM_BMAX);

    const int tid  = threadIdx.x;
    const int wid  = tid >> 5;
    const int lane = tid & 31;
    const int g    = lane >> 2;
    const int tg   = lane & 3;
    const int p    = tid & 127;   // staging/output point
    const int q4   = tid >> 7;    // staging/output channel quarter (0..3)

    // ---- stage B once: one code per thread; track ||bh||,||bl|| maxima ----
    {
        const int k = tid;        // 0..511
        const float4* e4 = (const float4*)(cb + k * D_);
        float ev[D_];
        #pragma unroll
        for (int i = 0; i < 16; i++) {
            float4 v = __ldg(e4 + i);
            ev[4*i] = v.x; ev[4*i+1] = v.y; ev[4*i+2] = v.z; ev[4*i+3] = v.w;
        }
        float s = 0.f;
        #pragma unroll
        for (int i = 0; i < D_; i++) s = __fadd_rn(s, __fmul_rn(ev[i], ev[i]));
        s_y[k] = s;
        if (blockIdx.x == 0) g_y[k] = s;
        float bhsq = 0.f, blsq = 0.f;
        #pragma unroll
        for (int j = 0; j < 32; j++) {
            float v0 = ev[2*j], v1 = ev[2*j+1];
            float h0 = __bfloat162float(__float2bfloat16(v0));
            float h1 = __bfloat162float(__float2bfloat16(v1));
            float l0 = v0 - h0, l1 = v1 - h1;
            bhsq = fmaf(h0, h0, fmaf(h1, h1, bhsq));
            blsq = fmaf(l0, l0, fmaf(l1, l1, blsq));
            uint32_t off = (uint32_t)(k * 128 + j * 4);
            *(uint32_t*)(smem + SM_BH + SWZ128(off)) = pack_bf16x2(h0, h1);
        }
        // block max of bhsq/blsq
        #pragma unroll
        for (int off = 16; off > 0; off >>= 1) {
            bhsq = fmaxf(bhsq, __shfl_xor_sync(0xffffffffu, bhsq, off));
            blsq = fmaxf(blsq, __shfl_xor_sync(0xffffffffu, blsq, off));
        }
        if (lane == 0) { s_m1[wid] = bhsq; s_m2[wid] = blsq; }
    }
    __syncthreads();
    if (tid == 0) {
        float bh = 0.f, bl = 0.f;
        #pragma unroll
        for (int i = 0; i < 16; i++) {
            bh = fmaxf(bh, s_m1[i]);
            bl = fmaxf(bl, s_m2[i]);
        }
        s_bmax[0] = sqrtf(bh);
        s_bmax[1] = sqrtf(bl);
    }
    __syncthreads();
    const float Bh = s_bmax[0];
    const float Bl = s_bmax[1];

    // warp roles: point rows (wid>>1)*16 + g / +8 ; code half nh
    const int row0 = (wid >> 1) * 16 + g;
    const int nh   = wid & 1;

    // ldmatrix lane addresses (per-thread constant column part)
    const int lr = lane & 7;
    const int ms = lane >> 3;
    const uint32_t colx0 = (uint32_t)((ms * 16) ^ (lr << 4));        // k-bytes 0..63
    const uint32_t colx1 = (uint32_t)((64 + ms * 16) ^ (lr << 4));   // k-bytes 64..127
    const uint32_t browz = (uint32_t)((nh * 256 + lr) * 128);

    for (int tile = blockIdx.x; tile < NTILES; tile += gridDim.x) {
        const int base = tile * 128;
        const int b    = base >> 12;
        const int hw0  = base & (HW_ - 1);
        const float* zb = z + (size_t)b * D_ * HW_ + hw0;

        // ---- stage A: z -> regs (fp32) + bf16-hi to smem; norm partials ----
        float zf[16];
        {
            const int c0s = q4 * 16;
            float pal = 0.f, pah = 0.f;
            #pragma unroll
            for (int j = 0; j < 8; j++) {
                int c = c0s + 2 * j;
                float v0 = __ldg(zb + (size_t)c * HW_ + p);
                float v1 = __ldg(zb + (size_t)(c + 1) * HW_ + p);
                zf[2*j] = v0; zf[2*j+1] = v1;
                float h0 = __bfloat162float(__float2bfloat16(v0));
                float h1 = __bfloat162float(__float2bfloat16(v1));
                float l0 = v0 - h0, l1 = v1 - h1;
                pah = fmaf(h0, h0, fmaf(h1, h1, pah));
                pal = fmaf(l0, l0, fmaf(l1, l1, pal));
                uint32_t off = (uint32_t)(p * 128 + c * 2);
                *(uint32_t*)(smem + SM_AHI + SWZ128(off)) = pack_bf16x2(h0, h1);
            }
            s_pal[q4 * 128 + p] = pal;
            s_pah[q4 * 128 + p] = pah;
        }
        __syncthreads();

        // ---- A fragments (validated layout) ----
        uint32_t ah[4][4];
        #pragma unroll
        for (int ks = 0; ks < 4; ks++) {
            uint32_t o = (uint32_t)(row0 * 128 + ks * 32 + tg * 4);
            ah[ks][0] = *(uint32_t*)(smem + SM_AHI + SWZ128(o));
            ah[ks][1] = *(uint32_t*)(smem + SM_AHI + SWZ128(o + 8 * 128));
            ah[ks][2] = *(uint32_t*)(smem + SM_AHI + SWZ128(o + 16));
            ah[ks][3] = *(uint32_t*)(smem + SM_AHI + SWZ128(o + 8 * 128 + 16));
        }

        uint32_t bh0 = smb + SM_BH + browz + colx0;
        uint32_t bh1 = smb + SM_BH + browz + colx1;

        float m1a = 3.4e38f, m2a = 3.4e38f;
        float m1b = 3.4e38f, m2b = 3.4e38f;
        int   k1a = K_, k1b = K_;

        #pragma unroll 4
        for (int nb = 0; nb < 32; nb++) {
            uint32_t h1[4], h2[4];
            ldsm_x4(h1, bh0); ldsm_x4(h2, bh1);
            bh0 += 1024; bh1 += 1024;

            float acc[4] = {0.f, 0.f, 0.f, 0.f};
            mma_bf16(acc, ah[0], h1[0], h1[1]);
            mma_bf16(acc, ah[1], h1[2], h1[3]);
            mma_bf16(acc, ah[2], h2[0], h2[1]);
            mma_bf16(acc, ah[3], h2[2], h2[3]);

            const int c0 = nh * 256 + nb * 8 + tg * 2;
            float2 y2 = *(const float2*)&s_y[c0];
            float t0 = fmaf(-2.f, acc[0], y2.x);
            float t1 = fmaf(-2.f, acc[1], y2.y);
            float t2 = fmaf(-2.f, acc[2], y2.x);
            float t3 = fmaf(-2.f, acc[3], y2.y);
            if (t0 < m1a) { m2a = m1a; m1a = t0; k1a = c0; }     else m2a = fminf(m2a, t0);
            if (t1 < m1a) { m2a = m1a; m1a = t1; k1a = c0 + 1; } else m2a = fminf(m2a, t1);
            if (t2 < m1b) { m2b = m1b; m1b = t2; k1b = c0; }     else m2b = fminf(m2b, t2);
            if (t3 < m1b) { m2b = m1b; m1b = t3; k1b = c0 + 1; } else m2b = fminf(m2b, t3);
        }

        // quad merge (tg bits)
        #pragma unroll
        for (int off = 1; off <= 2; off <<= 1) {
            float om1 = __shfl_xor_sync(0xffffffffu, m1a, off);
            int   ok1 = __shfl_xor_sync(0xffffffffu, k1a, off);
            float om2 = __shfl_xor_sync(0xffffffffu, m2a, off);
            merge3(m1a, k1a, m2a, om1, ok1, om2);
            om1 = __shfl_xor_sync(0xffffffffu, m1b, off);
            ok1 = __shfl_xor_sync(0xffffffffu, k1b, off);
            om2 = __shfl_xor_sync(0xffffffffu, m2b, off);
            merge3(m1b, k1b, m2b, om1, ok1, om2);
        }
        if (tg == 0) {
            s_m1[row0 * 2 + nh] = m1a; s_m2[row0 * 2 + nh] = m2a;
            s_k1[row0 * 2 + nh] = k1a;
            s_m1[(row0 + 8) * 2 + nh] = m1b; s_m2[(row0 + 8) * 2 + nh] = m2b;
            s_k1[(row0 + 8) * 2 + nh] = k1b;
        }
        __syncthreads();

        // ---- decision: merge halves, per-point provable window -> worklist ----
        if (tid < 128) {
            float m1 = s_m1[tid * 2], m2v = s_m2[tid * 2];
            int   k1 = s_k1[tid * 2];
            merge3(m1, k1, m2v, s_m1[tid*2+1], s_k1[tid*2+1], s_m2[tid*2+1]);
            // per-point dropped-term bound (Cauchy-Schwarz)
            float alsq = s_pal[tid] + s_pal[128 + tid]
                       + s_pal[256 + tid] + s_pal[384 + tid];
            float ahsq = s_pah[tid] + s_pah[128 + tid]
                       + s_pah[256 + tid] + s_pah[384 + tid];
            float al_n = sqrtf(alsq), ah_n = sqrtf(ahsq);
            float drop = al_n * Bh + (ah_n + al_n) * Bl;
            float W = 7.0e-5f + 4.4f * drop;
            int fl = (m2v - m1) < W;
            s_bkf[tid] = k1; s_flag[tid] = fl;
            if (fl) {
                int i = atomicAdd(&g_flag_count, 1);
                g_worklist[i] = base + tid;
            }
        }
        __syncthreads();

        // ---- output + loss (z from regs, codebook via LDG.128) ----
        float lsum = 0.f;
        if (!s_flag[p]) {
            const int bestk = s_bkf[p];
            const float4* e4 = (const float4*)(cb + bestk * D_);
            float* op = out + (size_t)b * D_ * HW_ + hw0 + p;
            #pragma unroll
            for (int j4 = 0; j4 < 4; j4++) {
                float4 e = __ldg(e4 + q4 * 4 + j4);
                #pragma unroll
                for (int u = 0; u < 4; u++) {
                    int c = q4 * 16 + 4 * j4 + u;
                    float qq = (u == 0) ? e.x : (u == 1) ? e.y : (u == 2) ? e.z : e.w;
                    float zv = zf[4 * j4 + u];
                    float dd = __fadd_rn(qq, -zv);
                    lsum = __fmaf_rn(dd, dd, lsum);
                    op[(size_t)c * HW_] = __fadd_rn(zv, dd);
                }
            }
        }
        #pragma unroll
        for (int off = 16; off > 0; off >>= 1)
            lsum += __shfl_down_sync(0xffffffffu, lsum, off);
        if (lane == 0) s_red[wid] = lsum;
        __syncthreads();
        if (tid == 0) {
            float v = 0.f;
            #pragma unroll
            for (int i = 0; i < 16; i++) v += s_red[i];
            atomicAdd(&g_loss_accum, (double)v);
        }
        __syncthreads();   // protect smem tiles before next tile's staging
    }
}

// ---------------- fallback: bit-exact full scan, one point per warp ----------------
#define FB_CTAS 64
#define FB_TPB  256
__global__ __launch_bounds__(FB_TPB)
void vq_fallback_kernel(const float* __restrict__ z,
                        const float* __restrict__ cb,
                        float* __restrict__ out) {
    const int lane = threadIdx.x & 31;
    const int gw   = (blockIdx.x * FB_TPB + threadIdx.x) >> 5;
    const int nw   = (FB_CTAS * FB_TPB) >> 5;
    const int cnt  = g_flag_count;

    for (int w = gw; w < cnt; w += nw) {
        const int n  = g_worklist[w];
        const int b  = n >> 12;
        const int hw = n & (HW_ - 1);
        const float* zp = z + (size_t)b * D_ * HW_ + hw;

        float zv[D_];
        #pragma unroll
        for (int i = 0; i < D_; i++) zv[i] = __ldg(zp + (size_t)i * HW_);
        float x = 0.f;
        #pragma unroll
        for (int i = 0; i < D_; i++) x = __fadd_rn(x, __fmul_rn(zv[i], zv[i]));

        // 4 codes concurrently (independent exact chains, per-code order preserved)
        float bd = 3.4e38f; int bk = K_;
        #pragma unroll 1
        for (int kk = 0; kk < 16; kk += 4) {
            const int k = lane * 16 + kk;
            const float4* r0 = (const float4*)(cb + (k + 0) * D_);
            const float4* r1 = (const float4*)(cb + (k + 1) * D_);
            const float4* r2 = (const float4*)(cb + (k + 2) * D_);
            const float4* r3 = (const float4*)(cb + (k + 3) * D_);
            float a0 = 0.f, a1 = 0.f, a2 = 0.f, a3 = 0.f;
            #pragma unroll
            for (int i = 0; i < 16; i++) {
                float4 e0 = __ldg(r0 + i), e1 = __ldg(r1 + i);
                float4 e2 = __ldg(r2 + i), e3 = __ldg(r3 + i);
                a0 = __fmaf_rn(zv[4*i+0], e0.x, a0);
                a1 = __fmaf_rn(zv[4*i+0], e1.x, a1);
                a2 = __fmaf_rn(zv[4*i+0], e2.x, a2);
                a3 = __fmaf_rn(zv[4*i+0], e3.x, a3);
                a0 = __fmaf_rn(zv[4*i+1], e0.y, a0);
                a1 = __fmaf_rn(zv[4*i+1], e1.y, a1);
                a2 = __fmaf_rn(zv[4*i+1], e2.y, a2);
                a3 = __fmaf_rn(zv[4*i+1], e3.y, a3);
                a0 = __fmaf_rn(zv[4*i+2], e0.z, a0);
                a1 = __fmaf_rn(zv[4*i+2], e1.z, a1);
                a2 = __fmaf_rn(zv[4*i+2], e2.z, a2);
                a3 = __fmaf_rn(zv[4*i+2], e3.z, a3);
                a0 = __fmaf_rn(zv[4*i+3], e0.w, a0);
                a1 = __fmaf_rn(zv[4*i+3], e1.w, a1);
                a2 = __fmaf_rn(zv[4*i+3], e2.w, a2);
                a3 = __fmaf_rn(zv[4*i+3], e3.w, a3);
            }
            float d0 = __fadd_rn(__fadd_rn(x, g_y[k + 0]), -__fmul_rn(2.f, a0));
            float d1 = __fadd_rn(__fadd_rn(x, g_y[k + 1]), -__fmul_rn(2.f, a1));
            float d2 = __fadd_rn(__fadd_rn(x, g_y[k + 2]), -__fmul_rn(2.f, a2));
            float d3 = __fadd_rn(__fadd_rn(x, g_y[k + 3]), -__fmul_rn(2.f, a3));
            if (d0 < bd) { bd = d0; bk = k + 0; }
            if (d1 < bd) { bd = d1; bk = k + 1; }
            if (d2 < bd) { bd = d2; bk = k + 2; }
            if (d3 < bd) { bd = d3; bk = k + 3; }
        }
        #pragma unroll
        for (int off = 16; off > 0; off >>= 1) {
            float od = __shfl_down_sync(0xffffffffu, bd, off);
            int   ok = __shfl_down_sync(0xffffffffu, bk, off);
            if (od < bd || (od == bd && ok < bk)) { bd = od; bk = ok; }
        }
        bk = __shfl_sync(0xffffffffu, bk, 0);

        float* op = out + (size_t)b * D_ * HW_ + hw;
        const float* e = cb + bk * D_;
        float ls = 0.f;
        #pragma unroll
        for (int h = 0; h < 2; h++) {
            int c = lane + 32 * h;
            float qq = __ldg(e + c);
            float dd = __fadd_rn(qq, -zv[c]);
            ls = __fmaf_rn(dd, dd, ls);
            op[(size_t)c * HW_] = __fadd_rn(zv[c], dd);
        }
        #pragma unroll
        for (int off = 16; off > 0; off >>= 1)
            ls += __shfl_down_sync(0xffffffffu, ls, off);
        if (lane == 0) atomicAdd(&g_loss_accum, (double)ls);
    }
}

// ---------------- finalize: write loss, reset state for graph replays ----------------
__global__ void vq_finalize_kernel(float* __restrict__ out, int loss_idx) {
    out[loss_idx] = (float)(g_loss_accum * 1.25 / (double)NELEM);
    g_loss_accum = 0.0;
    g_flag_count = 0;
}

extern "C" void kernel_launch(void* const* d_in, const int* in_sizes, int n_in,
                              void* d_out, int out_size) {
    const float* z  = (const float*)d_in[0];
    const float* cb = (const float*)d_in[1];
    float* out = (float*)d_out;

    static bool attr_set = false;
    if (!attr_set) {
        cudaFuncSetAttribute(vq_main_kernel,
                             cudaFuncAttributeMaxDynamicSharedMemorySize,
                             SMEM_TOTAL);
        attr_set = true;
    }

    vq_main_kernel<<<MGRID, MTPB, SMEM_TOTAL>>>(z, cb, out);
    vq_fallback_kernel<<<FB_CTAS, FB_TPB>>>(z, cb, out);
    vq_finalize_kernel<<<1, 1>>>(out, out_size - 1);
}

// round 10
// speedup vs baseline: 3.5461x; 3.5461x over previous
#include <cuda_runtime.h>
#include <cuda_fp16.h>
#include <cstdint>

// ---------------- problem constants ----------------
#define D_    64
#define HW_   4096
#define K_    512
#define NPTS  131072
#define NELEM 8388608LL

#define MTPB   512
#define MGRID  148
#define NTILES (NPTS / 128)   // 1024

// ---- smem byte offsets (A/B tiles 1024-aligned for SW128) ----
#define SM_Y     0        // 512 f32 (y_k + 1.0, screen only)
#define SM_BKF   2048     // 128 int
#define SM_FLAG  2560     // 128 int
#define SM_RED   3072     // 16 f32
#define SM_K1S   3136     // 256 u32 (per (row,nh) key1)
#define SM_K2S   4160     // 256 u32 (per (row,nh) key2)
#define SM_PX    5184     // 4*128 f32 (per (q4,p) partial ||z||^2)
#define SM_BMAX  7232     // 1 f32 (Bh)
#define SM_AHI   8192     // 128 rows * 128 B  fp16 z   (SW128)
#define SM_BH    24576    // 512 rows * 128 B  fp16 cb  (SW128)
#define SMEM_TOTAL 90112

// ---------------- device globals (zero-init; finalize resets) ----------------
__device__ double g_loss_accum;
__device__ int    g_flag_count;
__device__ int    g_worklist[NPTS];
__device__ float  g_y[K_];            // EXACT sequential sum e_i^2 (fallback)

#define SWZ128(off) ((off) ^ (((off) >> 3) & 0x70))

__device__ __forceinline__ uint32_t smem_u32_of(const void* p) {
    uint32_t a;
    asm("{ .reg .u64 t; cvta.to.shared.u64 t, %1; cvt.u32.u64 %0, t; }"
        : "=r"(a) : "l"(p));
    return a;
}
__device__ __forceinline__ void mma_f16(float* c, const uint32_t* a,
                                        uint32_t b0, uint32_t b1) {
    asm volatile(
        "mma.sync.aligned.m16n8k16.row.col.f32.f16.f16.f32 "
        "{%0,%1,%2,%3}, {%4,%5,%6,%7}, {%8,%9}, {%0,%1,%2,%3};"
        : "+f"(c[0]), "+f"(c[1]), "+f"(c[2]), "+f"(c[3])
        : "r"(a[0]), "r"(a[1]), "r"(a[2]), "r"(a[3]), "r"(b0), "r"(b1));
}
__device__ __forceinline__ void ldsm_x4(uint32_t* r, uint32_t addr) {
    asm volatile(
        "ldmatrix.sync.aligned.m8n8.x4.shared.b16 {%0,%1,%2,%3}, [%4];"
        : "=r"(r[0]), "=r"(r[1]), "=r"(r[2]), "=r"(r[3]) : "r"(addr));
}
__device__ __forceinline__ uint32_t pack_f16x2(float lo, float hi) {
    __half2 h = __floats2half2_rn(lo, hi);   // lo -> low 16 bits
    return *reinterpret_cast<uint32_t*>(&h);
}
// key = (fbits(t) & ~0x1FF) | k ; t > 0 so bits are monotone in t.
__device__ __forceinline__ uint32_t mkkey(float t, int k) {
    return (__float_as_uint(t) & 0xFFFFFE00u) | (uint32_t)k;
}
__device__ __forceinline__ void upd2(uint32_t key, uint32_t& k1, uint32_t& k2) {
    if (key < k1) { k2 = k1; k1 = key; } else k2 = min(k2, key);
}

// ---------------- main: persistent, single-pass fp16 screen ----------------
__global__ __launch_bounds__(MTPB, 1)
void vq_main_kernel(const float* __restrict__ z,
                    const float* __restrict__ cb,
                    float* __restrict__ out) {
    extern __shared__ char smem[];
    const uint32_t smb = smem_u32_of(smem);
    float*    s_y    = (float*)(smem + SM_Y);
    int*      s_bkf  = (int*)(smem + SM_BKF);
    int*      s_flag = (int*)(smem + SM_FLAG);
    float*    s_red  = (float*)(smem + SM_RED);
    uint32_t* s_k1s  = (uint32_t*)(smem + SM_K1S);
    uint32_t* s_k2s  = (uint32_t*)(smem + SM_K2S);
    float*    s_px   = (float*)(smem + SM_PX);
    float*    s_bmax = (float*)(smem + SM_BMAX);

    const int tid  = threadIdx.x;
    const int wid  = tid >> 5;
    const int lane = tid & 31;
    const int g    = lane >> 2;
    const int tg   = lane & 3;
    const int p    = tid & 127;   // staging/output point
    const int q4   = tid >> 7;    // staging/output channel quarter (0..3)

    // ---- stage B once: one code per thread; exact y; fp16 tile; max||e_h|| ----
    {
        const int k = tid;        // 0..511
        const float4* e4 = (const float4*)(cb + k * D_);
        float ev[D_];
        #pragma unroll
        for (int i = 0; i < 16; i++) {
            float4 v = __ldg(e4 + i);
            ev[4*i] = v.x; ev[4*i+1] = v.y; ev[4*i+2] = v.z; ev[4*i+3] = v.w;
        }
        float s = 0.f;
        #pragma unroll
        for (int i = 0; i < D_; i++) s = __fadd_rn(s, __fmul_rn(ev[i], ev[i]));
        if (blockIdx.x == 0) g_y[k] = s;
        s_y[k] = s + 1.0f;                     // screen constant (y+1)
        float bhsq = 0.f;
        #pragma unroll
        for (int j = 0; j < 32; j++) {
            float v0 = ev[2*j], v1 = ev[2*j+1];
            float h0 = __half2float(__float2half_rn(v0));
            float h1 = __half2float(__float2half_rn(v1));
            bhsq = fmaf(h0, h0, fmaf(h1, h1, bhsq));
            uint32_t off = (uint32_t)(k * 128 + j * 4);
            *(uint32_t*)(smem + SM_BH + SWZ128(off)) = pack_f16x2(v0, v1);
        }
        #pragma unroll
        for (int off = 16; off > 0; off >>= 1)
            bhsq = fmaxf(bhsq, __shfl_xor_sync(0xffffffffu, bhsq, off));
        if (lane == 0) s_red[wid] = bhsq;
    }
    __syncthreads();
    if (tid == 0) {
        float bh = 0.f;
        #pragma unroll
        for (int i = 0; i < 16; i++) bh = fmaxf(bh, s_red[i]);
        s_bmax[0] = sqrtf(bh);
    }
    __syncthreads();
    const float Wc = 4.2e-3f * s_bmax[0];   // window coefficient (x sqrt(px))

    // warp roles: point rows (wid>>1)*16 + g / +8 ; code half nh
    const int row0 = (wid >> 1) * 16 + g;
    const int nh   = wid & 1;

    // ldmatrix lane addresses (per-thread constant column part)
    const int lr = lane & 7;
    const int ms = lane >> 3;
    const uint32_t colx0 = (uint32_t)((ms * 16) ^ (lr << 4));        // k-bytes 0..63
    const uint32_t colx1 = (uint32_t)((64 + ms * 16) ^ (lr << 4));   // k-bytes 64..127
    const uint32_t browz = (uint32_t)((nh * 256 + lr) * 128);

    for (int tile = blockIdx.x; tile < NTILES; tile += gridDim.x) {
        const int base = tile * 128;
        const int b    = base >> 12;
        const int hw0  = base & (HW_ - 1);
        const float* zb = z + (size_t)b * D_ * HW_ + hw0;

        // ---- stage A: z -> regs (fp32) + fp16 to smem; ||z||^2 partials ----
        float zf[16];
        {
            const int c0s = q4 * 16;
            float px = 0.f;
            #pragma unroll
            for (int j = 0; j < 8; j++) {
                int c = c0s + 2 * j;
                float v0 = __ldg(zb + (size_t)c * HW_ + p);
                float v1 = __ldg(zb + (size_t)(c + 1) * HW_ + p);
                zf[2*j] = v0; zf[2*j+1] = v1;
                px = fmaf(v0, v0, fmaf(v1, v1, px));
                uint32_t off = (uint32_t)(p * 128 + c * 2);
                *(uint32_t*)(smem + SM_AHI + SWZ128(off)) = pack_f16x2(v0, v1);
            }
            s_px[q4 * 128 + p] = px;
        }
        __syncthreads();

        // ---- A fragments (validated layout) ----
        uint32_t ah[4][4];
        #pragma unroll
        for (int ks = 0; ks < 4; ks++) {
            uint32_t o = (uint32_t)(row0 * 128 + ks * 32 + tg * 4);
            ah[ks][0] = *(uint32_t*)(smem + SM_AHI + SWZ128(o));
            ah[ks][1] = *(uint32_t*)(smem + SM_AHI + SWZ128(o + 8 * 128));
            ah[ks][2] = *(uint32_t*)(smem + SM_AHI + SWZ128(o + 16));
            ah[ks][3] = *(uint32_t*)(smem + SM_AHI + SWZ128(o + 8 * 128 + 16));
        }

        uint32_t bh0 = smb + SM_BH + browz + colx0;
        uint32_t bh1 = smb + SM_BH + browz + colx1;

        uint32_t k1a = 0xFFFFFFFFu, k2a = 0xFFFFFFFFu;
        uint32_t k1b = 0xFFFFFFFFu, k2b = 0xFFFFFFFFu;

        #pragma unroll 4
        for (int nb = 0; nb < 32; nb++) {
            uint32_t h1[4], h2[4];
            ldsm_x4(h1, bh0); ldsm_x4(h2, bh1);
            bh0 += 1024; bh1 += 1024;

            float acc[4] = {0.f, 0.f, 0.f, 0.f};
            mma_f16(acc, ah[0], h1[0], h1[1]);
            mma_f16(acc, ah[1], h1[2], h1[3]);
            mma_f16(acc, ah[2], h2[0], h2[1]);
            mma_f16(acc, ah[3], h2[2], h2[3]);

            const int c0 = nh * 256 + nb * 8 + tg * 2;
            float2 y2 = *(const float2*)&s_y[c0];       // y+1
            float t0 = fmaf(-2.f, acc[0], y2.x);        // in [~0.7, ~1.3] > 0
            float t1 = fmaf(-2.f, acc[1], y2.y);
            float t2 = fmaf(-2.f, acc[2], y2.x);
            float t3 = fmaf(-2.f, acc[3], y2.y);
            upd2(mkkey(t0, c0),     k1a, k2a);
            upd2(mkkey(t1, c0 + 1), k1a, k2a);
            upd2(mkkey(t2, c0),     k1b, k2b);
            upd2(mkkey(t3, c0 + 1), k1b, k2b);
        }

        // quad merge (tg bits): min1/min2 on u32 keys
        #pragma unroll
        for (int off = 1; off <= 2; off <<= 1) {
            uint32_t n1 = __shfl_xor_sync(0xffffffffu, k1a, off);
            uint32_t n2 = __shfl_xor_sync(0xffffffffu, k2a, off);
            if (n1 < k1a) { k2a = min(k1a, n2); k1a = n1; } else k2a = min(k2a, n1);
            n1 = __shfl_xor_sync(0xffffffffu, k1b, off);
            n2 = __shfl_xor_sync(0xffffffffu, k2b, off);
            if (n1 < k1b) { k2b = min(k1b, n2); k1b = n1; } else k2b = min(k2b, n1);
        }
        if (tg == 0) {
            s_k1s[row0 * 2 + nh] = k1a; s_k2s[row0 * 2 + nh] = k2a;
            s_k1s[(row0 + 8) * 2 + nh] = k1b; s_k2s[(row0 + 8) * 2 + nh] = k2b;
        }
        __syncthreads();

        // ---- decision: merge halves, per-point provable window -> worklist ----
        if (tid < 128) {
            uint32_t a1 = s_k1s[tid * 2],     a2 = s_k2s[tid * 2];
            uint32_t b1 = s_k1s[tid * 2 + 1], b2 = s_k2s[tid * 2 + 1];
            if (b1 < a1) { a2 = min(a1, b2); a1 = b1; } else a2 = min(a2, b1);
            float f1 = __uint_as_float(a1 & 0xFFFFFE00u);
            float f2 = __uint_as_float(a2 & 0xFFFFFE00u);
            float px = s_px[tid] + s_px[128 + tid]
                     + s_px[256 + tid] + s_px[384 + tid];
            float W = 2.5e-4f + Wc * sqrtf(px);
            int fl = (f2 - f1) < W;
            s_bkf[tid] = (int)(a1 & 511u); s_flag[tid] = fl;
            if (fl) {
                int i = atomicAdd(&g_flag_count, 1);
                g_worklist[i] = base + tid;
            }
        }
        __syncthreads();

        // ---- output + loss (z from regs, codebook via LDG.128) ----
        float lsum = 0.f;
        if (!s_flag[p]) {
            const int bestk = s_bkf[p];
            const float4* e4 = (const float4*)(cb + bestk * D_);
            float* op = out + (size_t)b * D_ * HW_ + hw0 + p;
            #pragma unroll
            for (int j4 = 0; j4 < 4; j4++) {
                float4 e = __ldg(e4 + q4 * 4 + j4);
                #pragma unroll
                for (int u = 0; u < 4; u++) {
                    int c = q4 * 16 + 4 * j4 + u;
                    float qq = (u == 0) ? e.x : (u == 1) ? e.y : (u == 2) ? e.z : e.w;
                    float zv = zf[4 * j4 + u];
                    float dd = __fadd_rn(qq, -zv);
                    lsum = __fmaf_rn(dd, dd, lsum);
                    op[(size_t)c * HW_] = __fadd_rn(zv, dd);
                }
            }
        }
        #pragma unroll
        for (int off = 16; off > 0; off >>= 1)
            lsum += __shfl_down_sync(0xffffffffu, lsum, off);
        if (lane == 0) s_red[wid] = lsum;
        __syncthreads();
        if (tid == 0) {
            float v = 0.f;
            #pragma unroll
            for (int i = 0; i < 16; i++) v += s_red[i];
            atomicAdd(&g_loss_accum, (double)v);
        }
        __syncthreads();   // protect smem tiles before next tile's staging
    }
}

// ---------------- fallback: bit-exact full scan, one point per warp ----------------
#define FB_CTAS 128
#define FB_TPB  256
__global__ __launch_bounds__(FB_TPB)
void vq_fallback_kernel(const float* __restrict__ z,
                        const float* __restrict__ cb,
                        float* __restrict__ out) {
    const int lane = threadIdx.x & 31;
    const int gw   = (blockIdx.x * FB_TPB + threadIdx.x) >> 5;
    const int nw   = (FB_CTAS * FB_TPB) >> 5;   // 1024 warps
    const int cnt  = g_flag_count;

    float ls_tot = 0.f;   // batched loss (ONE atomic per warp at the end)

    for (int w = gw; w < cnt; w += nw) {
        const int n  = g_worklist[w];
        const int b  = n >> 12;
        const int hw = n & (HW_ - 1);
        const float* zp = z + (size_t)b * D_ * HW_ + hw;

        float zv[D_];
        #pragma unroll
        for (int i = 0; i < D_; i++) zv[i] = __ldg(zp + (size_t)i * HW_);
        float x = 0.f;
        #pragma unroll
        for (int i = 0; i < D_; i++) x = __fadd_rn(x, __fmul_rn(zv[i], zv[i]));

        // 4 codes concurrently (independent exact chains, per-code order preserved)
        float bd = 3.4e38f; int bk = K_;
        #pragma unroll 1
        for (int kk = 0; kk < 16; kk += 4) {
            const int k = lane * 16 + kk;
            const float4* r0 = (const float4*)(cb + (k + 0) * D_);
            const float4* r1 = (const float4*)(cb + (k + 1) * D_);
            const float4* r2 = (const float4*)(cb + (k + 2) * D_);
            const float4* r3 = (const float4*)(cb + (k + 3) * D_);
            float a0 = 0.f, a1 = 0.f, a2 = 0.f, a3 = 0.f;
            #pragma unroll
            for (int i = 0; i < 16; i++) {
                float4 e0 = __ldg(r0 + i), e1 = __ldg(r1 + i);
                float4 e2 = __ldg(r2 + i), e3 = __ldg(r3 + i);
                a0 = __fmaf_rn(zv[4*i+0], e0.x, a0);
                a1 = __fmaf_rn(zv[4*i+0], e1.x, a1);
                a2 = __fmaf_rn(zv[4*i+0], e2.x, a2);
                a3 = __fmaf_rn(zv[4*i+0], e3.x, a3);
                a0 = __fmaf_rn(zv[4*i+1], e0.y, a0);
                a1 = __fmaf_rn(zv[4*i+1], e1.y, a1);
                a2 = __fmaf_rn(zv[4*i+1], e2.y, a2);
                a3 = __fmaf_rn(zv[4*i+1], e3.y, a3);
                a0 = __fmaf_rn(zv[4*i+2], e0.z, a0);
                a1 = __fmaf_rn(zv[4*i+2], e1.z, a1);
                a2 = __fmaf_rn(zv[4*i+2], e2.z, a2);
                a3 = __fmaf_rn(zv[4*i+2], e3.z, a3);
                a0 = __fmaf_rn(zv[4*i+3], e0.w, a0);
                a1 = __fmaf_rn(zv[4*i+3], e1.w, a1);
                a2 = __fmaf_rn(zv[4*i+3], e2.w, a2);
                a3 = __fmaf_rn(zv[4*i+3], e3.w, a3);
            }
            float d0 = __fadd_rn(__fadd_rn(x, g_y[k + 0]), -__fmul_rn(2.f, a0));
            float d1 = __fadd_rn(__fadd_rn(x, g_y[k + 1]), -__fmul_rn(2.f, a1));
            float d2 = __fadd_rn(__fadd_rn(x, g_y[k + 2]), -__fmul_rn(2.f, a2));
            float d3 = __fadd_rn(__fadd_rn(x, g_y[k + 3]), -__fmul_rn(2.f, a3));
            if (d0 < bd) { bd = d0; bk = k + 0; }
            if (d1 < bd) { bd = d1; bk = k + 1; }
            if (d2 < bd) { bd = d2; bk = k + 2; }
            if (d3 < bd) { bd = d3; bk = k + 3; }
        }
        #pragma unroll
        for (int off = 16; off > 0; off >>= 1) {
            float od = __shfl_down_sync(0xffffffffu, bd, off);
            int   ok = __shfl_down_sync(0xffffffffu, bk, off);
            if (od < bd || (od == bd && ok < bk)) { bd = od; bk = ok; }
        }
        bk = __shfl_sync(0xffffffffu, bk, 0);

        float* op = out + (size_t)b * D_ * HW_ + hw;
        const float* e = cb + bk * D_;
        #pragma unroll
        for (int h = 0; h < 2; h++) {
            int c = lane + 32 * h;
            float qq = __ldg(e + c);
            float dd = __fadd_rn(qq, -zv[c]);
            ls_tot = __fmaf_rn(dd, dd, ls_tot);
            op[(size_t)c * HW_] = __fadd_rn(zv[c], dd);
        }
    }

    // one atomic per warp
    #pragma unroll
    for (int off = 16; off > 0; off >>= 1)
        ls_tot += __shfl_down_sync(0xffffffffu, ls_tot, off);
    if (lane == 0 && ls_tot != 0.f)
        atomicAdd(&g_loss_accum, (double)ls_tot);
}

// ---------------- finalize: write loss, reset state for graph replays ----------------
__global__ void vq_finalize_kernel(float* __restrict__ out, int loss_idx) {
    out[loss_idx] = (float)(g_loss_accum * 1.25 / (double)NELEM);
    g_loss_accum = 0.0;
    g_flag_count = 0;
}

extern "C" void kernel_launch(void* const* d_in, const int* in_sizes, int n_in,
                              void* d_out, int out_size) {
    const float* z  = (const float*)d_in[0];
    const float* cb = (const float*)d_in[1];
    float* out = (float*)d_out;

    static bool attr_set = false;
    if (!attr_set) {
        cudaFuncSetAttribute(vq_main_kernel,
                             cudaFuncAttributeMaxDynamicSharedMemorySize,
                             SMEM_TOTAL);
        attr_set = true;
    }

    vq_main_kernel<<<MGRID, MTPB, SMEM_TOTAL>>>(z, cb, out);
    vq_fallback_kernel<<<FB_CTAS, FB_TPB>>>(z, cb, out);
    vq_finalize_kernel<<<1, 1>>>(out, out_size - 1);
}

// round 11
// speedup vs baseline: 9.4811x; 2.6737x over previous
#include <cuda_runtime.h>
#include <cuda_fp16.h>
#include <cstdint>

// ---------------- problem constants ----------------
#define D_    64
#define HW_   4096
#define K_    512
#define NPTS  131072
#define NELEM 8388608LL

#define MTPB   512
#define MGRID  148
#define NTILES (NPTS / 128)   // 1024

// ---- smem byte offsets (A/B tiles 1024-aligned for SW128) ----
#define SM_Y     0        // 512 f32 (y_k + 0.5, screen only)
#define SM_BKF   2048     // 128 int
#define SM_FLAG  2560     // 128 int
#define SM_RED   3072     // 16 f32
#define SM_K1S   3136     // 256 u32
#define SM_K2S   4160     // 256 u32
#define SM_PX    5184     // 4*128 f32 (per (q4,p) partial ||z||^2)
#define SM_BMAX  7232     // 1 f32 (El)
#define SM_AHI   8192     // 128 rows * 128 B  fp16 z-hi (SW128)
#define SM_ALO   24576    // 128 rows * 128 B  fp16 z-lo (SW128)
#define SM_BH    40960    // 512 rows * 128 B  fp16 cb   (SW128)
#define SMEM_TOTAL 106496

// ---------------- device globals (zero-init; finalize resets) ----------------
__device__ double g_loss_accum;
__device__ int    g_flag_count;
__device__ int    g_worklist[NPTS];
__device__ float  g_y[K_];            // EXACT sequential sum e_i^2 (fallback)

#define SWZ128(off) ((off) ^ (((off) >> 3) & 0x70))

__device__ __forceinline__ uint32_t smem_u32_of(const void* p) {
    uint32_t a;
    asm("{ .reg .u64 t; cvta.to.shared.u64 t, %1; cvt.u32.u64 %0, t; }"
        : "=r"(a) : "l"(p));
    return a;
}
__device__ __forceinline__ void mma_f16(float* c, const uint32_t* a,
                                        uint32_t b0, uint32_t b1) {
    asm volatile(
        "mma.sync.aligned.m16n8k16.row.col.f32.f16.f16.f32 "
        "{%0,%1,%2,%3}, {%4,%5,%6,%7}, {%8,%9}, {%0,%1,%2,%3};"
        : "+f"(c[0]), "+f"(c[1]), "+f"(c[2]), "+f"(c[3])
        : "r"(a[0]), "r"(a[1]), "r"(a[2]), "r"(a[3]), "r"(b0), "r"(b1));
}
__device__ __forceinline__ void ldsm_x4(uint32_t* r, uint32_t addr) {
    asm volatile(
        "ldmatrix.sync.aligned.m8n8.x4.shared.b16 {%0,%1,%2,%3}, [%4];"
        : "=r"(r[0]), "=r"(r[1]), "=r"(r[2]), "=r"(r[3]) : "r"(addr));
}
__device__ __forceinline__ uint32_t pack_f16x2(float lo, float hi) {
    __half2 h = __floats2half2_rn(lo, hi);   // lo -> low 16 bits
    return *reinterpret_cast<uint32_t*>(&h);
}
// key = (fbits(t) & ~0x1FF) | k ; t > 0 so bits are monotone in t.
__device__ __forceinline__ uint32_t mkkey(float t, int k) {
    return (__float_as_uint(t) & 0xFFFFFE00u) | (uint32_t)k;
}
__device__ __forceinline__ void upd2(uint32_t key, uint32_t& k1, uint32_t& k2) {
    if (key < k1) { k2 = k1; k1 = key; } else k2 = min(k2, key);
}

// ---------------- main: persistent, 2-pass fp16 split screen ----------------
__global__ __launch_bounds__(MTPB, 1)
void vq_main_kernel(const float* __restrict__ z,
                    const float* __restrict__ cb,
                    float* __restrict__ out) {
    extern __shared__ char smem[];
    const uint32_t smb = smem_u32_of(smem);
    float*    s_y    = (float*)(smem + SM_Y);
    int*      s_bkf  = (int*)(smem + SM_BKF);
    int*      s_flag = (int*)(smem + SM_FLAG);
    float*    s_red  = (float*)(smem + SM_RED);
    uint32_t* s_k1s  = (uint32_t*)(smem + SM_K1S);
    uint32_t* s_k2s  = (uint32_t*)(smem + SM_K2S);
    float*    s_px   = (float*)(smem + SM_PX);
    float*    s_bmax = (float*)(smem + SM_BMAX);

    const int tid  = threadIdx.x;
    const int wid  = tid >> 5;
    const int lane = tid & 31;
    const int g    = lane >> 2;
    const int tg   = lane & 3;
    const int p    = tid & 127;   // staging/output point
    const int q4   = tid >> 7;    // staging/output channel quarter (0..3)

    // ---- stage B once: exact y; fp16 tile; exact max ||e - fp16(e)|| ----
    {
        const int k = tid;        // 0..511
        const float4* e4 = (const float4*)(cb + k * D_);
        float ev[D_];
        #pragma unroll
        for (int i = 0; i < 16; i++) {
            float4 v = __ldg(e4 + i);
            ev[4*i] = v.x; ev[4*i+1] = v.y; ev[4*i+2] = v.z; ev[4*i+3] = v.w;
        }
        float s = 0.f;
        #pragma unroll
        for (int i = 0; i < D_; i++) s = __fadd_rn(s, __fmul_rn(ev[i], ev[i]));
        if (blockIdx.x == 0) g_y[k] = s;
        s_y[k] = s + 0.5f;                     // screen constant (y + 0.5)
        float elsq = 0.f;
        #pragma unroll
        for (int j = 0; j < 32; j++) {
            float v0 = ev[2*j], v1 = ev[2*j+1];
            float h0 = __half2float(__float2half_rn(v0));
            float h1 = __half2float(__float2half_rn(v1));
            float l0 = v0 - h0, l1 = v1 - h1;
            elsq = fmaf(l0, l0, fmaf(l1, l1, elsq));
            uint32_t off = (uint32_t)(k * 128 + j * 4);
            *(uint32_t*)(smem + SM_BH + SWZ128(off)) = pack_f16x2(v0, v1);
        }
        #pragma unroll
        for (int off = 16; off > 0; off >>= 1)
            elsq = fmaxf(elsq, __shfl_xor_sync(0xffffffffu, elsq, off));
        if (lane == 0) s_red[wid] = elsq;
    }
    __syncthreads();
    if (tid == 0) {
        float m = 0.f;
        #pragma unroll
        for (int i = 0; i < 16; i++) m = fmaxf(m, s_red[i]);
        s_bmax[0] = sqrtf(m) * 1.001f;         // El with tiny safety
    }
    __syncthreads();
    const float El = s_bmax[0];

    // warp roles: point rows (wid>>1)*16 + g / +8 ; code half nh
    const int row0 = (wid >> 1) * 16 + g;
    const int nh   = wid & 1;

    // ldmatrix lane addresses (per-thread constant column part)
    const int lr = lane & 7;
    const int ms = lane >> 3;
    const uint32_t colx0 = (uint32_t)((ms * 16) ^ (lr << 4));        // k-bytes 0..63
    const uint32_t colx1 = (uint32_t)((64 + ms * 16) ^ (lr << 4));   // k-bytes 64..127
    const uint32_t browz = (uint32_t)((nh * 256 + lr) * 128);

    for (int tile = blockIdx.x; tile < NTILES; tile += gridDim.x) {
        const int base = tile * 128;
        const int b    = base >> 12;
        const int hw0  = base & (HW_ - 1);
        const float* zb = z + (size_t)b * D_ * HW_ + hw0;

        // ---- stage A: z -> fp16 hi + fp16 residual tiles; ||z||^2 partials ----
        {
            const int c0s = q4 * 16;
            float px = 0.f;
            #pragma unroll
            for (int j = 0; j < 8; j++) {
                int c = c0s + 2 * j;
                float v0 = __ldg(zb + (size_t)c * HW_ + p);
                float v1 = __ldg(zb + (size_t)(c + 1) * HW_ + p);
                px = fmaf(v0, v0, fmaf(v1, v1, px));
                float h0 = __half2float(__float2half_rn(v0));
                float h1 = __half2float(__float2half_rn(v1));
                uint32_t off = (uint32_t)(p * 128 + c * 2);
                *(uint32_t*)(smem + SM_AHI + SWZ128(off)) = pack_f16x2(v0, v1);
                *(uint32_t*)(smem + SM_ALO + SWZ128(off)) =
                    pack_f16x2(v0 - h0, v1 - h1);
            }
            s_px[q4 * 128 + p] = px;
        }
        __syncthreads();

        // ---- A fragments (validated layout): hi + lo ----
        uint32_t ah[4][4], al[4][4];
        #pragma unroll
        for (int ks = 0; ks < 4; ks++) {
            uint32_t o = (uint32_t)(row0 * 128 + ks * 32 + tg * 4);
            ah[ks][0] = *(uint32_t*)(smem + SM_AHI + SWZ128(o));
            ah[ks][1] = *(uint32_t*)(smem + SM_AHI + SWZ128(o + 8 * 128));
            ah[ks][2] = *(uint32_t*)(smem + SM_AHI + SWZ128(o + 16));
            ah[ks][3] = *(uint32_t*)(smem + SM_AHI + SWZ128(o + 8 * 128 + 16));
            al[ks][0] = *(uint32_t*)(smem + SM_ALO + SWZ128(o));
            al[ks][1] = *(uint32_t*)(smem + SM_ALO + SWZ128(o + 8 * 128));
            al[ks][2] = *(uint32_t*)(smem + SM_ALO + SWZ128(o + 16));
            al[ks][3] = *(uint32_t*)(smem + SM_ALO + SWZ128(o + 8 * 128 + 16));
        }

        uint32_t bh0 = smb + SM_BH + browz + colx0;
        uint32_t bh1 = smb + SM_BH + browz + colx1;

        uint32_t k1a = 0xFFFFFFFFu, k2a = 0xFFFFFFFFu;
        uint32_t k1b = 0xFFFFFFFFu, k2b = 0xFFFFFFFFu;

        #pragma unroll 4
        for (int nb = 0; nb < 32; nb++) {
            uint32_t h1[4], h2[4];
            ldsm_x4(h1, bh0); ldsm_x4(h2, bh1);
            bh0 += 1024; bh1 += 1024;

            float acc[4] = {0.f, 0.f, 0.f, 0.f};
            mma_f16(acc, ah[0], h1[0], h1[1]);
            mma_f16(acc, al[0], h1[0], h1[1]);
            mma_f16(acc, ah[1], h1[2], h1[3]);
            mma_f16(acc, al[1], h1[2], h1[3]);
            mma_f16(acc, ah[2], h2[0], h2[1]);
            mma_f16(acc, al[2], h2[0], h2[1]);
            mma_f16(acc, ah[3], h2[2], h2[3]);
            mma_f16(acc, al[3], h2[2], h2[3]);

            const int c0 = nh * 256 + nb * 8 + tg * 2;
            float2 y2 = *(const float2*)&s_y[c0];       // y + 0.5
            float t0 = fmaf(-2.f, acc[0], y2.x);        // in [~0.1, ~0.9] > 0
            float t1 = fmaf(-2.f, acc[1], y2.y);
            float t2 = fmaf(-2.f, acc[2], y2.x);
            float t3 = fmaf(-2.f, acc[3], y2.y);
            upd2(mkkey(t0, c0),     k1a, k2a);
            upd2(mkkey(t1, c0 + 1), k1a, k2a);
            upd2(mkkey(t2, c0),     k1b, k2b);
            upd2(mkkey(t3, c0 + 1), k1b, k2b);
        }

        // quad merge (tg bits): min1/min2 on u32 keys
        #pragma unroll
        for (int off = 1; off <= 2; off <<= 1) {
            uint32_t n1 = __shfl_xor_sync(0xffffffffu, k1a, off);
            uint32_t n2 = __shfl_xor_sync(0xffffffffu, k2a, off);
            if (n1 < k1a) { k2a = min(k1a, n2); k1a = n1; } else k2a = min(k2a, n1);
            n1 = __shfl_xor_sync(0xffffffffu, k1b, off);
            n2 = __shfl_xor_sync(0xffffffffu, k2b, off);
            if (n1 < k1b) { k2b = min(k1b, n2); k1b = n1; } else k2b = min(k2b, n1);
        }
        if (tg == 0) {
            s_k1s[row0 * 2 + nh] = k1a; s_k2s[row0 * 2 + nh] = k2a;
            s_k1s[(row0 + 8) * 2 + nh] = k1b; s_k2s[(row0 + 8) * 2 + nh] = k2b;
        }
        __syncthreads();

        // ---- decision: merge halves, rigorous per-point window -> worklist ----
        if (tid < 128) {
            uint32_t a1 = s_k1s[tid * 2],     a2 = s_k2s[tid * 2];
            uint32_t b1 = s_k1s[tid * 2 + 1], b2 = s_k2s[tid * 2 + 1];
            if (b1 < a1) { a2 = min(a1, b2); a1 = b1; } else a2 = min(a2, b1);
            float f1 = __uint_as_float(a1 & 0xFFFFFE00u);
            float f2 = __uint_as_float(a2 & 0xFFFFFE00u);
            float px = s_px[tid] + s_px[128 + tid]
                     + s_px[256 + tid] + s_px[384 + tid];
            // grid rounding of reference distances (2 values, tier by x)
            float gridw = (px < 63.7f) ? 1.7e-5f : (px < 127.7f ? 3.3e-5f : 6.6e-5f);
            // + key quantization (<=3.05e-5 for t<1) + dropped-term bound
            float W = gridw + 3.3e-5f + 2.6f * sqrtf(px) * El;
            int fl = (f2 - f1) < W;
            s_bkf[tid] = (int)(a1 & 511u); s_flag[tid] = fl;
            if (fl) {
                int i = atomicAdd(&g_flag_count, 1);
                g_worklist[i] = base + tid;
            }
        }
        __syncthreads();

        // ---- output + loss (z reloaded from gmem/L2, codebook via LDG.128) ----
        float lsum = 0.f;
        if (!s_flag[p]) {
            const int bestk = s_bkf[p];
            const float4* e4 = (const float4*)(cb + bestk * D_);
            float* op = out + (size_t)b * D_ * HW_ + hw0 + p;
            #pragma unroll
            for (int j4 = 0; j4 < 4; j4++) {
                float4 e = __ldg(e4 + q4 * 4 + j4);
                #pragma unroll
                for (int u = 0; u < 4; u++) {
                    int c = q4 * 16 + 4 * j4 + u;
                    float qq = (u == 0) ? e.x : (u == 1) ? e.y : (u == 2) ? e.z : e.w;
                    float zv = __ldg(zb + (size_t)c * HW_ + p);
                    float dd = __fadd_rn(qq, -zv);
                    lsum = __fmaf_rn(dd, dd, lsum);
                    op[(size_t)c * HW_] = __fadd_rn(zv, dd);
                }
            }
        }
        #pragma unroll
        for (int off = 16; off > 0; off >>= 1)
            lsum += __shfl_down_sync(0xffffffffu, lsum, off);
        if (lane == 0) s_red[wid] = lsum;
        __syncthreads();
        if (tid == 0) {
            float v = 0.f;
            #pragma unroll
            for (int i = 0; i < 16; i++) v += s_red[i];
            atomicAdd(&g_loss_accum, (double)v);
        }
        __syncthreads();   // protect smem tiles before next tile's staging
    }
}

// ---------------- fallback: bit-exact full scan, one point per warp ----------------
#define FB_CTAS 128
#define FB_TPB  256
__global__ __launch_bounds__(FB_TPB)
void vq_fallback_kernel(const float* __restrict__ z,
                        const float* __restrict__ cb,
                        float* __restrict__ out) {
    const int lane = threadIdx.x & 31;
    const int gw   = (blockIdx.x * FB_TPB + threadIdx.x) >> 5;
    const int nw   = (FB_CTAS * FB_TPB) >> 5;   // 1024 warps
    const int cnt  = g_flag_count;

    float ls_tot = 0.f;   // batched loss (ONE atomic per warp at the end)

    for (int w = gw; w < cnt; w += nw) {
        const int n  = g_worklist[w];
        const int b  = n >> 12;
        const int hw = n & (HW_ - 1);
        const float* zp = z + (size_t)b * D_ * HW_ + hw;

        float zv[D_];
        #pragma unroll
        for (int i = 0; i < D_; i++) zv[i] = __ldg(zp + (size_t)i * HW_);
        float x = 0.f;
        #pragma unroll
        for (int i = 0; i < D_; i++) x = __fadd_rn(x, __fmul_rn(zv[i], zv[i]));

        // 4 codes concurrently (independent exact chains, per-code order preserved)
        float bd = 3.4e38f; int bk = K_;
        #pragma unroll 1
        for (int kk = 0; kk < 16; kk += 4) {
            const int k = lane * 16 + kk;
            const float4* r0 = (const float4*)(cb + (k + 0) * D_);
            const float4* r1 = (const float4*)(cb + (k + 1) * D_);
            const float4* r2 = (const float4*)(cb + (k + 2) * D_);
            const float4* r3 = (const float4*)(cb + (k + 3) * D_);
            float a0 = 0.f, a1 = 0.f, a2 = 0.f, a3 = 0.f;
            #pragma unroll
            for (int i = 0; i < 16; i++) {
                float4 e0 = __ldg(r0 + i), e1 = __ldg(r1 + i);
                float4 e2 = __ldg(r2 + i), e3 = __ldg(r3 + i);
                a0 = __fmaf_rn(zv[4*i+0], e0.x, a0);
                a1 = __fmaf_rn(zv[4*i+0], e1.x, a1);
                a2 = __fmaf_rn(zv[4*i+0], e2.x, a2);
                a3 = __fmaf_rn(zv[4*i+0], e3.x, a3);
                a0 = __fmaf_rn(zv[4*i+1], e0.y, a0);
                a1 = __fmaf_rn(zv[4*i+1], e1.y, a1);
                a2 = __fmaf_rn(zv[4*i+1], e2.y, a2);
                a3 = __fmaf_rn(zv[4*i+1], e3.y, a3);
                a0 = __fmaf_rn(zv[4*i+2], e0.z, a0);
                a1 = __fmaf_rn(zv[4*i+2], e1.z, a1);
                a2 = __fmaf_rn(zv[4*i+2], e2.z, a2);
                a3 = __fmaf_rn(zv[4*i+2], e3.z, a3);
                a0 = __fmaf_rn(zv[4*i+3], e0.w, a0);
                a1 = __fmaf_rn(zv[4*i+3], e1.w, a1);
                a2 = __fmaf_rn(zv[4*i+3], e2.w, a2);
                a3 = __fmaf_rn(zv[4*i+3], e3.w, a3);
            }
            float d0 = __fadd_rn(__fadd_rn(x, g_y[k + 0]), -__fmul_rn(2.f, a0));
            float d1 = __fadd_rn(__fadd_rn(x, g_y[k + 1]), -__fmul_rn(2.f, a1));
            float d2 = __fadd_rn(__fadd_rn(x, g_y[k + 2]), -__fmul_rn(2.f, a2));
            float d3 = __fadd_rn(__fadd_rn(x, g_y[k + 3]), -__fmul_rn(2.f, a3));
            if (d0 < bd) { bd = d0; bk = k + 0; }
            if (d1 < bd) { bd = d1; bk = k + 1; }
            if (d2 < bd) { bd = d2; bk = k + 2; }
            if (d3 < bd) { bd = d3; bk = k + 3; }
        }
        #pragma unroll
        for (int off = 16; off > 0; off >>= 1) {
            float od = __shfl_down_sync(0xffffffffu, bd, off);
            int   ok = __shfl_down_sync(0xffffffffu, bk, off);
            if (od < bd || (od == bd && ok < bk)) { bd = od; bk = ok; }
        }
        bk = __shfl_sync(0xffffffffu, bk, 0);

        float* op = out + (size_t)b * D_ * HW_ + hw;
        const float* e = cb + bk * D_;
        #pragma unroll
        for (int h = 0; h < 2; h++) {
            int c = lane + 32 * h;
            float qq = __ldg(e + c);
            float dd = __fadd_rn(qq, -zv[c]);
            ls_tot = __fmaf_rn(dd, dd, ls_tot);
            op[(size_t)c * HW_] = __fadd_rn(zv[c], dd);
        }
    }

    // one atomic per warp
    #pragma unroll
    for (int off = 16; off > 0; off >>= 1)
        ls_tot += __shfl_down_sync(0xffffffffu, ls_tot, off);
    if (lane == 0 && ls_tot != 0.f)
        atomicAdd(&g_loss_accum, (double)ls_tot);
}

// ---------------- finalize: write loss, reset state for graph replays ----------------
__global__ void vq_finalize_kernel(float* __restrict__ out, int loss_idx) {
    out[loss_idx] = (float)(g_loss_accum * 1.25 / (double)NELEM);
    g_loss_accum = 0.0;
    g_flag_count = 0;
}

extern "C" void kernel_launch(void* const* d_in, const int* in_sizes, int n_in,
                              void* d_out, int out_size) {
    const float* z  = (const float*)d_in[0];
    const float* cb = (const float*)d_in[1];
    float* out = (float*)d_out;

    static bool attr_set = false;
    if (!attr_set) {
        cudaFuncSetAttribute(vq_main_kernel,
                             cudaFuncAttributeMaxDynamicSharedMemorySize,
                             SMEM_TOTAL);
        attr_set = true;
    }

    vq_main_kernel<<<MGRID, MTPB, SMEM_TOTAL>>>(z, cb, out);
    vq_fallback_kernel<<<FB_CTAS, FB_TPB>>>(z, cb, out);
    vq_finalize_kernel<<<1, 1>>>(out, out_size - 1);
}

// round 12
// speedup vs baseline: 10.3333x; 1.0899x over previous
#include <cuda_runtime.h>
#include <cuda_fp16.h>
#include <cstdint>

// ---------------- problem constants ----------------
#define D_    64
#define HW_   4096
#define K_    512
#define NPTS  131072
#define NELEM 8388608LL

#define MTPB   512
#define MGRID  148
#define NTILES (NPTS / 128)   // 1024

// ---- smem byte offsets (A/B tiles 1024-aligned for SW128) ----
#define SM_Y     0        // 512 f32 (y_k + 0.5, screen only)
#define SM_BKF   2048     // 128 int
#define SM_FLAG  2560     // 128 int
#define SM_RED   3072     // 16 f32
#define SM_K1S   3136     // 256 u32
#define SM_K2S   4160     // 256 u32
#define SM_PX    5184     // 4*128 f32 (per (q4,p) partial ||z||^2)
#define SM_BMAX  7232     // 1 f32 (El)
#define SM_AHI   8192     // 128 rows * 128 B  fp16 z-hi (SW128)
#define SM_ALO   24576    // 128 rows * 128 B  fp16 z-lo (SW128)
#define SM_BH    40960    // 512 rows * 128 B  fp16 cb   (SW128)
#define SMEM_TOTAL 106496

// fallback smem: fp32 codebook + exact y
#define FB_SMEM (K_ * D_ * 4 + K_ * 4)   // 133120 B

// ---------------- device globals (zero-init; finalize resets) ----------------
__device__ double g_loss_accum;
__device__ int    g_flag_count;
__device__ int    g_worklist[NPTS];
__device__ float  g_y[K_];            // EXACT sequential sum e_i^2 (fallback)

#define SWZ128(off) ((off) ^ (((off) >> 3) & 0x70))

__device__ __forceinline__ uint32_t smem_u32_of(const void* p) {
    uint32_t a;
    asm("{ .reg .u64 t; cvta.to.shared.u64 t, %1; cvt.u32.u64 %0, t; }"
        : "=r"(a) : "l"(p));
    return a;
}
__device__ __forceinline__ void mma_f16(float* c, const uint32_t* a,
                                        uint32_t b0, uint32_t b1) {
    asm volatile(
        "mma.sync.aligned.m16n8k16.row.col.f32.f16.f16.f32 "
        "{%0,%1,%2,%3}, {%4,%5,%6,%7}, {%8,%9}, {%0,%1,%2,%3};"
        : "+f"(c[0]), "+f"(c[1]), "+f"(c[2]), "+f"(c[3])
        : "r"(a[0]), "r"(a[1]), "r"(a[2]), "r"(a[3]), "r"(b0), "r"(b1));
}
__device__ __forceinline__ void ldsm_x4(uint32_t* r, uint32_t addr) {
    asm volatile(
        "ldmatrix.sync.aligned.m8n8.x4.shared.b16 {%0,%1,%2,%3}, [%4];"
        : "=r"(r[0]), "=r"(r[1]), "=r"(r[2]), "=r"(r[3]) : "r"(addr));
}
__device__ __forceinline__ uint32_t pack_f16x2(float lo, float hi) {
    __half2 h = __floats2half2_rn(lo, hi);   // lo -> low 16 bits
    return *reinterpret_cast<uint32_t*>(&h);
}
// key = (fbits(t) & ~0x1FF) | k ; t > 0 so bits are monotone in t.
__device__ __forceinline__ uint32_t mkkey(float t, int k) {
    return (__float_as_uint(t) & 0xFFFFFE00u) | (uint32_t)k;
}
__device__ __forceinline__ void upd2(uint32_t key, uint32_t& k1, uint32_t& k2) {
    if (key < k1) { k2 = k1; k1 = key; } else k2 = min(k2, key);
}

// ---------------- main: persistent, 2-pass fp16 split screen (R11, unchanged) ----------------
__global__ __launch_bounds__(MTPB, 1)
void vq_main_kernel(const float* __restrict__ z,
                    const float* __restrict__ cb,
                    float* __restrict__ out) {
    extern __shared__ char smem[];
    const uint32_t smb = smem_u32_of(smem);
    float*    s_y    = (float*)(smem + SM_Y);
    int*      s_bkf  = (int*)(smem + SM_BKF);
    int*      s_flag = (int*)(smem + SM_FLAG);
    float*    s_red  = (float*)(smem + SM_RED);
    uint32_t* s_k1s  = (uint32_t*)(smem + SM_K1S);
    uint32_t* s_k2s  = (uint32_t*)(smem + SM_K2S);
    float*    s_px   = (float*)(smem + SM_PX);
    float*    s_bmax = (float*)(smem + SM_BMAX);

    const int tid  = threadIdx.x;
    const int wid  = tid >> 5;
    const int lane = tid & 31;
    const int g    = lane >> 2;
    const int tg   = lane & 3;
    const int p    = tid & 127;   // staging/output point
    const int q4   = tid >> 7;    // staging/output channel quarter (0..3)

    // ---- stage B once: exact y; fp16 tile; exact max ||e - fp16(e)|| ----
    {
        const int k = tid;        // 0..511
        const float4* e4 = (const float4*)(cb + k * D_);
        float ev[D_];
        #pragma unroll
        for (int i = 0; i < 16; i++) {
            float4 v = __ldg(e4 + i);
            ev[4*i] = v.x; ev[4*i+1] = v.y; ev[4*i+2] = v.z; ev[4*i+3] = v.w;
        }
        float s = 0.f;
        #pragma unroll
        for (int i = 0; i < D_; i++) s = __fadd_rn(s, __fmul_rn(ev[i], ev[i]));
        if (blockIdx.x == 0) g_y[k] = s;
        s_y[k] = s + 0.5f;                     // screen constant (y + 0.5)
        float elsq = 0.f;
        #pragma unroll
        for (int j = 0; j < 32; j++) {
            float v0 = ev[2*j], v1 = ev[2*j+1];
            float h0 = __half2float(__float2half_rn(v0));
            float h1 = __half2float(__float2half_rn(v1));
            float l0 = v0 - h0, l1 = v1 - h1;
            elsq = fmaf(l0, l0, fmaf(l1, l1, elsq));
            uint32_t off = (uint32_t)(k * 128 + j * 4);
            *(uint32_t*)(smem + SM_BH + SWZ128(off)) = pack_f16x2(v0, v1);
        }
        #pragma unroll
        for (int off = 16; off > 0; off >>= 1)
            elsq = fmaxf(elsq, __shfl_xor_sync(0xffffffffu, elsq, off));
        if (lane == 0) s_red[wid] = elsq;
    }
    __syncthreads();
    if (tid == 0) {
        float m = 0.f;
        #pragma unroll
        for (int i = 0; i < 16; i++) m = fmaxf(m, s_red[i]);
        s_bmax[0] = sqrtf(m) * 1.001f;         // El with tiny safety
    }
    __syncthreads();
    const float El = s_bmax[0];

    // warp roles: point rows (wid>>1)*16 + g / +8 ; code half nh
    const int row0 = (wid >> 1) * 16 + g;
    const int nh   = wid & 1;

    // ldmatrix lane addresses (per-thread constant column part)
    const int lr = lane & 7;
    const int ms = lane >> 3;
    const uint32_t colx0 = (uint32_t)((ms * 16) ^ (lr << 4));        // k-bytes 0..63
    const uint32_t colx1 = (uint32_t)((64 + ms * 16) ^ (lr << 4));   // k-bytes 64..127
    const uint32_t browz = (uint32_t)((nh * 256 + lr) * 128);

    for (int tile = blockIdx.x; tile < NTILES; tile += gridDim.x) {
        const int base = tile * 128;
        const int b    = base >> 12;
        const int hw0  = base & (HW_ - 1);
        const float* zb = z + (size_t)b * D_ * HW_ + hw0;

        // ---- stage A: z -> fp16 hi + fp16 residual tiles; ||z||^2 partials ----
        {
            const int c0s = q4 * 16;
            float px = 0.f;
            #pragma unroll
            for (int j = 0; j < 8; j++) {
                int c = c0s + 2 * j;
                float v0 = __ldg(zb + (size_t)c * HW_ + p);
                float v1 = __ldg(zb + (size_t)(c + 1) * HW_ + p);
                px = fmaf(v0, v0, fmaf(v1, v1, px));
                float h0 = __half2float(__float2half_rn(v0));
                float h1 = __half2float(__float2half_rn(v1));
                uint32_t off = (uint32_t)(p * 128 + c * 2);
                *(uint32_t*)(smem + SM_AHI + SWZ128(off)) = pack_f16x2(v0, v1);
                *(uint32_t*)(smem + SM_ALO + SWZ128(off)) =
                    pack_f16x2(v0 - h0, v1 - h1);
            }
            s_px[q4 * 128 + p] = px;
        }
        __syncthreads();

        // ---- A fragments (validated layout): hi + lo ----
        uint32_t ah[4][4], al[4][4];
        #pragma unroll
        for (int ks = 0; ks < 4; ks++) {
            uint32_t o = (uint32_t)(row0 * 128 + ks * 32 + tg * 4);
            ah[ks][0] = *(uint32_t*)(smem + SM_AHI + SWZ128(o));
            ah[ks][1] = *(uint32_t*)(smem + SM_AHI + SWZ128(o + 8 * 128));
            ah[ks][2] = *(uint32_t*)(smem + SM_AHI + SWZ128(o + 16));
            ah[ks][3] = *(uint32_t*)(smem + SM_AHI + SWZ128(o + 8 * 128 + 16));
            al[ks][0] = *(uint32_t*)(smem + SM_ALO + SWZ128(o));
            al[ks][1] = *(uint32_t*)(smem + SM_ALO + SWZ128(o + 8 * 128));
            al[ks][2] = *(uint32_t*)(smem + SM_ALO + SWZ128(o + 16));
            al[ks][3] = *(uint32_t*)(smem + SM_ALO + SWZ128(o + 8 * 128 + 16));
        }

        uint32_t bh0 = smb + SM_BH + browz + colx0;
        uint32_t bh1 = smb + SM_BH + browz + colx1;

        uint32_t k1a = 0xFFFFFFFFu, k2a = 0xFFFFFFFFu;
        uint32_t k1b = 0xFFFFFFFFu, k2b = 0xFFFFFFFFu;

        #pragma unroll 4
        for (int nb = 0; nb < 32; nb++) {
            uint32_t h1[4], h2[4];
            ldsm_x4(h1, bh0); ldsm_x4(h2, bh1);
            bh0 += 1024; bh1 += 1024;

            float acc[4] = {0.f, 0.f, 0.f, 0.f};
            mma_f16(acc, ah[0], h1[0], h1[1]);
            mma_f16(acc, al[0], h1[0], h1[1]);
            mma_f16(acc, ah[1], h1[2], h1[3]);
            mma_f16(acc, al[1], h1[2], h1[3]);
            mma_f16(acc, ah[2], h2[0], h2[1]);
            mma_f16(acc, al[2], h2[0], h2[1]);
            mma_f16(acc, ah[3], h2[2], h2[3]);
            mma_f16(acc, al[3], h2[2], h2[3]);

            const int c0 = nh * 256 + nb * 8 + tg * 2;
            float2 y2 = *(const float2*)&s_y[c0];       // y + 0.5
            float t0 = fmaf(-2.f, acc[0], y2.x);        // in [~0.1, ~0.9] > 0
            float t1 = fmaf(-2.f, acc[1], y2.y);
            float t2 = fmaf(-2.f, acc[2], y2.x);
            float t3 = fmaf(-2.f, acc[3], y2.y);
            upd2(mkkey(t0, c0),     k1a, k2a);
            upd2(mkkey(t1, c0 + 1), k1a, k2a);
            upd2(mkkey(t2, c0),     k1b, k2b);
            upd2(mkkey(t3, c0 + 1), k1b, k2b);
        }

        // quad merge (tg bits): min1/min2 on u32 keys
        #pragma unroll
        for (int off = 1; off <= 2; off <<= 1) {
            uint32_t n1 = __shfl_xor_sync(0xffffffffu, k1a, off);
            uint32_t n2 = __shfl_xor_sync(0xffffffffu, k2a, off);
            if (n1 < k1a) { k2a = min(k1a, n2); k1a = n1; } else k2a = min(k2a, n1);
            n1 = __shfl_xor_sync(0xffffffffu, k1b, off);
            n2 = __shfl_xor_sync(0xffffffffu, k2b, off);
            if (n1 < k1b) { k2b = min(k1b, n2); k1b = n1; } else k2b = min(k2b, n1);
        }
        if (tg == 0) {
            s_k1s[row0 * 2 + nh] = k1a; s_k2s[row0 * 2 + nh] = k2a;
            s_k1s[(row0 + 8) * 2 + nh] = k1b; s_k2s[(row0 + 8) * 2 + nh] = k2b;
        }
        __syncthreads();

        // ---- decision: merge halves, rigorous per-point window -> worklist ----
        if (tid < 128) {
            uint32_t a1 = s_k1s[tid * 2],     a2 = s_k2s[tid * 2];
            uint32_t b1 = s_k1s[tid * 2 + 1], b2 = s_k2s[tid * 2 + 1];
            if (b1 < a1) { a2 = min(a1, b2); a1 = b1; } else a2 = min(a2, b1);
            float f1 = __uint_as_float(a1 & 0xFFFFFE00u);
            float f2 = __uint_as_float(a2 & 0xFFFFFE00u);
            float px = s_px[tid] + s_px[128 + tid]
                     + s_px[256 + tid] + s_px[384 + tid];
            float gridw = (px < 63.7f) ? 1.7e-5f : (px < 127.7f ? 3.3e-5f : 6.6e-5f);
            float W = gridw + 3.3e-5f + 2.6f * sqrtf(px) * El;
            int fl = (f2 - f1) < W;
            s_bkf[tid] = (int)(a1 & 511u); s_flag[tid] = fl;
            if (fl) {
                int i = atomicAdd(&g_flag_count, 1);
                g_worklist[i] = base + tid;
            }
        }
        __syncthreads();

        // ---- output + loss (z reloaded from gmem/L2, codebook via LDG.128) ----
        float lsum = 0.f;
        if (!s_flag[p]) {
            const int bestk = s_bkf[p];
            const float4* e4 = (const float4*)(cb + bestk * D_);
            float* op = out + (size_t)b * D_ * HW_ + hw0 + p;
            #pragma unroll
            for (int j4 = 0; j4 < 4; j4++) {
                float4 e = __ldg(e4 + q4 * 4 + j4);
                #pragma unroll
                for (int u = 0; u < 4; u++) {
                    int c = q4 * 16 + 4 * j4 + u;
                    float qq = (u == 0) ? e.x : (u == 1) ? e.y : (u == 2) ? e.z : e.w;
                    float zv = __ldg(zb + (size_t)c * HW_ + p);
                    float dd = __fadd_rn(qq, -zv);
                    lsum = __fmaf_rn(dd, dd, lsum);
                    op[(size_t)c * HW_] = __fadd_rn(zv, dd);
                }
            }
        }
        #pragma unroll
        for (int off = 16; off > 0; off >>= 1)
            lsum += __shfl_down_sync(0xffffffffu, lsum, off);
        if (lane == 0) s_red[wid] = lsum;
        __syncthreads();
        if (tid == 0) {
            float v = 0.f;
            #pragma unroll
            for (int i = 0; i < 16; i++) v += s_red[i];
            atomicAdd(&g_loss_accum, (double)v);
        }
        __syncthreads();   // protect smem tiles before next tile's staging
    }
}

// ---------------- fallback v2: one point per THREAD, smem codebook (broadcast LDS) ----------------
#define FB_CTAS 148
#define FB_TPB  256
__global__ __launch_bounds__(FB_TPB, 1)
void vq_fallback_kernel(const float* __restrict__ z,
                        const float* __restrict__ cb,
                        float* __restrict__ out) {
    extern __shared__ float fsm[];
    float* s_cb = fsm;            // 512*64 fp32
    float* s_y  = fsm + K_ * D_;  // 512 fp32 (exact)

    const int tid  = threadIdx.x;
    const int lane = tid & 31;

    // stage codebook + y
    {
        const float4* g4 = (const float4*)cb;
        float4* s4 = (float4*)s_cb;
        for (int i = tid; i < K_ * D_ / 4; i += FB_TPB) s4[i] = g4[i];
        for (int i = tid; i < K_; i += FB_TPB) s_y[i] = g_y[i];
    }
    __syncthreads();

    const int cnt = g_flag_count;
    float ls_tot = 0.f;   // batched loss, ONE atomic per warp at the end

    for (int idx = blockIdx.x * FB_TPB + tid; idx < cnt; idx += FB_CTAS * FB_TPB) {
        const int n  = g_worklist[idx];
        const int b  = n >> 12;
        const int hw = n & (HW_ - 1);
        const float* zp = z + (size_t)b * D_ * HW_ + hw;

        float zv[D_];
        #pragma unroll
        for (int i = 0; i < D_; i++) zv[i] = __ldg(zp + (size_t)i * HW_);
        float x = 0.f;
        #pragma unroll
        for (int i = 0; i < D_; i++) x = __fadd_rn(x, __fmul_rn(zv[i], zv[i]));

        // bit-exact reference scan (R2-validated): 4 codes in flight,
        // per-code sequential fma chain, strict < keeps first index.
        float bd = 3.4e38f; int bk = 0;
        const float4* cb4 = (const float4*)s_cb;
        #pragma unroll 1
        for (int k = 0; k < K_; k += 4) {
            const float4* r0 = cb4 + (k + 0) * 16;
            const float4* r1 = cb4 + (k + 1) * 16;
            const float4* r2 = cb4 + (k + 2) * 16;
            const float4* r3 = cb4 + (k + 3) * 16;
            float a0 = 0.f, a1 = 0.f, a2 = 0.f, a3 = 0.f;
            #pragma unroll
            for (int i = 0; i < 16; i++) {
                float4 e0 = r0[i], e1 = r1[i], e2 = r2[i], e3 = r3[i];
                a0 = __fmaf_rn(zv[4*i+0], e0.x, a0);
                a1 = __fmaf_rn(zv[4*i+0], e1.x, a1);
                a2 = __fmaf_rn(zv[4*i+0], e2.x, a2);
                a3 = __fmaf_rn(zv[4*i+0], e3.x, a3);
                a0 = __fmaf_rn(zv[4*i+1], e0.y, a0);
                a1 = __fmaf_rn(zv[4*i+1], e1.y, a1);
                a2 = __fmaf_rn(zv[4*i+1], e2.y, a2);
                a3 = __fmaf_rn(zv[4*i+1], e3.y, a3);
                a0 = __fmaf_rn(zv[4*i+2], e0.z, a0);
                a1 = __fmaf_rn(zv[4*i+2], e1.z, a1);
                a2 = __fmaf_rn(zv[4*i+2], e2.z, a2);
                a3 = __fmaf_rn(zv[4*i+2], e3.z, a3);
                a0 = __fmaf_rn(zv[4*i+3], e0.w, a0);
                a1 = __fmaf_rn(zv[4*i+3], e1.w, a1);
                a2 = __fmaf_rn(zv[4*i+3], e2.w, a2);
                a3 = __fmaf_rn(zv[4*i+3], e3.w, a3);
            }
            float d0 = __fadd_rn(__fadd_rn(x, s_y[k + 0]), -__fmul_rn(2.f, a0));
            float d1 = __fadd_rn(__fadd_rn(x, s_y[k + 1]), -__fmul_rn(2.f, a1));
            float d2 = __fadd_rn(__fadd_rn(x, s_y[k + 2]), -__fmul_rn(2.f, a2));
            float d3 = __fadd_rn(__fadd_rn(x, s_y[k + 3]), -__fmul_rn(2.f, a3));
            if (d0 < bd) { bd = d0; bk = k + 0; }
            if (d1 < bd) { bd = d1; bk = k + 1; }
            if (d2 < bd) { bd = d2; bk = k + 2; }
            if (d3 < bd) { bd = d3; bk = k + 3; }
        }

        // output + loss
        float* op = out + (size_t)b * D_ * HW_ + hw;
        const float* e = s_cb + bk * D_;
        #pragma unroll
        for (int i = 0; i < D_; i++) {
            float dd = __fadd_rn(e[i], -zv[i]);
            ls_tot = __fmaf_rn(dd, dd, ls_tot);
            op[(size_t)i * HW_] = __fadd_rn(zv[i], dd);
        }
    }

    #pragma unroll
    for (int off = 16; off > 0; off >>= 1)
        ls_tot += __shfl_down_sync(0xffffffffu, ls_tot, off);
    if (lane == 0 && ls_tot != 0.f)
        atomicAdd(&g_loss_accum, (double)ls_tot);
}

// ---------------- finalize: write loss, reset state for graph replays ----------------
__global__ void vq_finalize_kernel(float* __restrict__ out, int loss_idx) {
    out[loss_idx] = (float)(g_loss_accum * 1.25 / (double)NELEM);
    g_loss_accum = 0.0;
    g_flag_count = 0;
}

extern "C" void kernel_launch(void* const* d_in, const int* in_sizes, int n_in,
                              void* d_out, int out_size) {
    const float* z  = (const float*)d_in[0];
    const float* cb = (const float*)d_in[1];
    float* out = (float*)d_out;

    static bool attr_set = false;
    if (!attr_set) {
        cudaFuncSetAttribute(vq_main_kernel,
                             cudaFuncAttributeMaxDynamicSharedMemorySize,
                             SMEM_TOTAL);
        cudaFuncSetAttribute(vq_fallback_kernel,
                             cudaFuncAttributeMaxDynamicSharedMemorySize,
                             FB_SMEM);
        attr_set = true;
    }

    vq_main_kernel<<<MGRID, MTPB, SMEM_TOTAL>>>(z, cb, out);
    vq_fallback_kernel<<<FB_CTAS, FB_TPB, FB_SMEM>>>(z, cb, out);
    vq_finalize_kernel<<<1, 1>>>(out, out_size - 1);
}

// round 13
// speedup vs baseline: 16.8228x; 1.6280x over previous
#include <cuda_runtime.h>
#include <cuda_fp16.h>
#include <cstdint>

// ---------------- problem constants ----------------
#define D_    64
#define HW_   4096
#define K_    512
#define NPTS  131072
#define NELEM 8388608LL

#define MTPB   512
#define MGRID  148
#define NTILES (NPTS / 128)   // 1024

// ---- main smem byte offsets (A/B tiles 1024-aligned for SW128) ----
#define SM_Y     0        // 512 f32 (y + 0.5, screen)
#define SM_YE    2048     // 512 f32 (exact y)
#define SM_BKF   4096     // 128 int
#define SM_FLAG  4608     // 128 int
#define SM_RED   5120     // 16 f32
#define SM_K1S   5184     // 256 u32
#define SM_K2S   6208     // 256 u32
#define SM_K3S   7232     // 256 u32
#define SM_PX    8256     // 4*128 f32
#define SM_BMAX  10304    // 1 f32 (El)
#define SM_AHI   12288    // 128*128 B fp16 z-hi (SW128)
#define SM_ALO   28672    // 128*128 B fp16 z-lo (SW128)
#define SM_BH    45056    // 512*128 B fp16 cb  (SW128)
#define SMEM_TOTAL 110592

// fallback smem: padded fp32 codebook [512][65] + exact y
#define FB_SMEM (K_ * 65 * 4 + K_ * 4)   // 135168 B

// ---------------- device globals (zero-init; finalize resets) ----------------
__device__ double g_loss_accum;
__device__ int    g_cnt_full;
__device__ int    g_cnt_pair;
__device__ int    g_wl_full[NPTS];
__device__ int    g_wl_pair[NPTS];
__device__ int    g_wl_pairk[NPTS];
__device__ float  g_y[K_];            // EXACT sequential sum e_i^2

#define SWZ128(off) ((off) ^ (((off) >> 3) & 0x70))

__device__ __forceinline__ uint32_t smem_u32_of(const void* p) {
    uint32_t a;
    asm("{ .reg .u64 t; cvta.to.shared.u64 t, %1; cvt.u32.u64 %0, t; }"
        : "=r"(a) : "l"(p));
    return a;
}
__device__ __forceinline__ void mma_f16(float* c, const uint32_t* a,
                                        uint32_t b0, uint32_t b1) {
    asm volatile(
        "mma.sync.aligned.m16n8k16.row.col.f32.f16.f16.f32 "
        "{%0,%1,%2,%3}, {%4,%5,%6,%7}, {%8,%9}, {%0,%1,%2,%3};"
        : "+f"(c[0]), "+f"(c[1]), "+f"(c[2]), "+f"(c[3])
        : "r"(a[0]), "r"(a[1]), "r"(a[2]), "r"(a[3]), "r"(b0), "r"(b1));
}
__device__ __forceinline__ void ldsm_x4(uint32_t* r, uint32_t addr) {
    asm volatile(
        "ldmatrix.sync.aligned.m8n8.x4.shared.b16 {%0,%1,%2,%3}, [%4];"
        : "=r"(r[0]), "=r"(r[1]), "=r"(r[2]), "=r"(r[3]) : "r"(addr));
}
__device__ __forceinline__ uint32_t pack_f16x2(float lo, float hi) {
    __half2 h = __floats2half2_rn(lo, hi);
    return *reinterpret_cast<uint32_t*>(&h);
}
// key = (fbits(t) & ~0x1FF) | k ; t > 0 -> monotone; ties -> smaller k.
__device__ __forceinline__ uint32_t mkkey(float t, int k) {
    return (__float_as_uint(t) & 0xFFFFFE00u) | (uint32_t)k;
}
// Insert key into sorted top-3 (branchless).
__device__ __forceinline__ void upd3(uint32_t key, uint32_t& k1,
                                     uint32_t& k2, uint32_t& k3) {
    k3 = min(k3, max(k2, key));
    k2 = min(k2, max(k1, key));
    k1 = min(k1, key);
}

// ---------------- main: persistent, 2-pass fp16 split screen + top-3 ----------------
__global__ __launch_bounds__(MTPB, 1)
void vq_main_kernel(const float* __restrict__ z,
                    const float* __restrict__ cb,
                    float* __restrict__ out) {
    extern __shared__ char smem[];
    const uint32_t smb = smem_u32_of(smem);
    float*    s_y    = (float*)(smem + SM_Y);
    float*    s_ye   = (float*)(smem + SM_YE);
    int*      s_bkf  = (int*)(smem + SM_BKF);
    int*      s_flag = (int*)(smem + SM_FLAG);
    float*    s_red  = (float*)(smem + SM_RED);
    uint32_t* s_k1s  = (uint32_t*)(smem + SM_K1S);
    uint32_t* s_k2s  = (uint32_t*)(smem + SM_K2S);
    uint32_t* s_k3s  = (uint32_t*)(smem + SM_K3S);
    float*    s_px   = (float*)(smem + SM_PX);
    float*    s_bmax = (float*)(smem + SM_BMAX);

    const int tid  = threadIdx.x;
    const int wid  = tid >> 5;
    const int lane = tid & 31;
    const int g    = lane >> 2;
    const int tg   = lane & 3;
    const int p    = tid & 127;
    const int q4   = tid >> 7;

    // ---- stage B once: exact y; fp16 tile; exact max ||e - fp16(e)|| ----
    {
        const int k = tid;        // 0..511
        const float4* e4 = (const float4*)(cb + k * D_);
        float ev[D_];
        #pragma unroll
        for (int i = 0; i < 16; i++) {
            float4 v = __ldg(e4 + i);
            ev[4*i] = v.x; ev[4*i+1] = v.y; ev[4*i+2] = v.z; ev[4*i+3] = v.w;
        }
        float s = 0.f;
        #pragma unroll
        for (int i = 0; i < D_; i++) s = __fadd_rn(s, __fmul_rn(ev[i], ev[i]));
        if (blockIdx.x == 0) g_y[k] = s;
        s_ye[k] = s;
        s_y[k]  = s + 0.5f;
        float elsq = 0.f;
        #pragma unroll
        for (int j = 0; j < 32; j++) {
            float v0 = ev[2*j], v1 = ev[2*j+1];
            float h0 = __half2float(__float2half_rn(v0));
            float h1 = __half2float(__float2half_rn(v1));
            float l0 = v0 - h0, l1 = v1 - h1;
            elsq = fmaf(l0, l0, fmaf(l1, l1, elsq));
            uint32_t off = (uint32_t)(k * 128 + j * 4);
            *(uint32_t*)(smem + SM_BH + SWZ128(off)) = pack_f16x2(v0, v1);
        }
        #pragma unroll
        for (int off = 16; off > 0; off >>= 1)
            elsq = fmaxf(elsq, __shfl_xor_sync(0xffffffffu, elsq, off));
        if (lane == 0) s_red[wid] = elsq;
    }
    __syncthreads();
    if (tid == 0) {
        float m = 0.f;
        #pragma unroll
        for (int i = 0; i < 16; i++) m = fmaxf(m, s_red[i]);
        s_bmax[0] = sqrtf(m) * 1.001f;
    }
    __syncthreads();
    const float El = s_bmax[0];

    const int row0 = (wid >> 1) * 16 + g;
    const int nh   = wid & 1;
    const int lr = lane & 7;
    const int ms = lane >> 3;
    const uint32_t colx0 = (uint32_t)((ms * 16) ^ (lr << 4));
    const uint32_t colx1 = (uint32_t)((64 + ms * 16) ^ (lr << 4));
    const uint32_t browz = (uint32_t)((nh * 256 + lr) * 128);

    for (int tile = blockIdx.x; tile < NTILES; tile += gridDim.x) {
        const int base = tile * 128;
        const int b    = base >> 12;
        const int hw0  = base & (HW_ - 1);
        const float* zb = z + (size_t)b * D_ * HW_ + hw0;

        // ---- stage A ----
        {
            const int c0s = q4 * 16;
            float px = 0.f;
            #pragma unroll
            for (int j = 0; j < 8; j++) {
                int c = c0s + 2 * j;
                float v0 = __ldg(zb + (size_t)c * HW_ + p);
                float v1 = __ldg(zb + (size_t)(c + 1) * HW_ + p);
                px = fmaf(v0, v0, fmaf(v1, v1, px));
                float h0 = __half2float(__float2half_rn(v0));
                float h1 = __half2float(__float2half_rn(v1));
                uint32_t off = (uint32_t)(p * 128 + c * 2);
                *(uint32_t*)(smem + SM_AHI + SWZ128(off)) = pack_f16x2(v0, v1);
                *(uint32_t*)(smem + SM_ALO + SWZ128(off)) =
                    pack_f16x2(v0 - h0, v1 - h1);
            }
            s_px[q4 * 128 + p] = px;
        }
        __syncthreads();

        // ---- A fragments (validated layout) ----
        uint32_t ah[4][4], al[4][4];
        #pragma unroll
        for (int ks = 0; ks < 4; ks++) {
            uint32_t o = (uint32_t)(row0 * 128 + ks * 32 + tg * 4);
            ah[ks][0] = *(uint32_t*)(smem + SM_AHI + SWZ128(o));
            ah[ks][1] = *(uint32_t*)(smem + SM_AHI + SWZ128(o + 8 * 128));
            ah[ks][2] = *(uint32_t*)(smem + SM_AHI + SWZ128(o + 16));
            ah[ks][3] = *(uint32_t*)(smem + SM_AHI + SWZ128(o + 8 * 128 + 16));
            al[ks][0] = *(uint32_t*)(smem + SM_ALO + SWZ128(o));
            al[ks][1] = *(uint32_t*)(smem + SM_ALO + SWZ128(o + 8 * 128));
            al[ks][2] = *(uint32_t*)(smem + SM_ALO + SWZ128(o + 16));
            al[ks][3] = *(uint32_t*)(smem + SM_ALO + SWZ128(o + 8 * 128 + 16));
        }

        uint32_t bh0 = smb + SM_BH + browz + colx0;
        uint32_t bh1 = smb + SM_BH + browz + colx1;

        uint32_t k1a = 0xFFFFFFFFu, k2a = 0xFFFFFFFFu, k3a = 0xFFFFFFFFu;
        uint32_t k1b = 0xFFFFFFFFu, k2b = 0xFFFFFFFFu, k3b = 0xFFFFFFFFu;

        #pragma unroll 4
        for (int nb = 0; nb < 32; nb++) {
            uint32_t h1[4], h2[4];
            ldsm_x4(h1, bh0); ldsm_x4(h2, bh1);
            bh0 += 1024; bh1 += 1024;

            float acc[4] = {0.f, 0.f, 0.f, 0.f};
            mma_f16(acc, ah[0], h1[0], h1[1]);
            mma_f16(acc, al[0], h1[0], h1[1]);
            mma_f16(acc, ah[1], h1[2], h1[3]);
            mma_f16(acc, al[1], h1[2], h1[3]);
            mma_f16(acc, ah[2], h2[0], h2[1]);
            mma_f16(acc, al[2], h2[0], h2[1]);
            mma_f16(acc, ah[3], h2[2], h2[3]);
            mma_f16(acc, al[3], h2[2], h2[3]);

            const int c0 = nh * 256 + nb * 8 + tg * 2;
            float2 y2 = *(const float2*)&s_y[c0];       // y + 0.5
            float t0 = fmaf(-2.f, acc[0], y2.x);        // > 0
            float t1 = fmaf(-2.f, acc[1], y2.y);
            float t2 = fmaf(-2.f, acc[2], y2.x);
            float t3 = fmaf(-2.f, acc[3], y2.y);
            upd3(mkkey(t0, c0),     k1a, k2a, k3a);
            upd3(mkkey(t1, c0 + 1), k1a, k2a, k3a);
            upd3(mkkey(t2, c0),     k1b, k2b, k3b);
            upd3(mkkey(t3, c0 + 1), k1b, k2b, k3b);
        }

        // quad merge (tg bits): top-3 on u32 keys
        #pragma unroll
        for (int off = 1; off <= 2; off <<= 1) {
            uint32_t n1 = __shfl_xor_sync(0xffffffffu, k1a, off);
            uint32_t n2 = __shfl_xor_sync(0xffffffffu, k2a, off);
            uint32_t n3 = __shfl_xor_sync(0xffffffffu, k3a, off);
            upd3(n1, k1a, k2a, k3a); upd3(n2, k1a, k2a, k3a);
            upd3(n3, k1a, k2a, k3a);
            n1 = __shfl_xor_sync(0xffffffffu, k1b, off);
            n2 = __shfl_xor_sync(0xffffffffu, k2b, off);
            n3 = __shfl_xor_sync(0xffffffffu, k3b, off);
            upd3(n1, k1b, k2b, k3b); upd3(n2, k1b, k2b, k3b);
            upd3(n3, k1b, k2b, k3b);
        }
        if (tg == 0) {
            s_k1s[row0 * 2 + nh] = k1a; s_k2s[row0 * 2 + nh] = k2a;
            s_k3s[row0 * 2 + nh] = k3a;
            s_k1s[(row0 + 8) * 2 + nh] = k1b; s_k2s[(row0 + 8) * 2 + nh] = k2b;
            s_k3s[(row0 + 8) * 2 + nh] = k3b;
        }
        __syncthreads();

        // ---- decision: merge halves, 3-tier resolution ----
        if (tid < 128) {
            uint32_t a1 = s_k1s[tid * 2], a2 = s_k2s[tid * 2], a3 = s_k3s[tid * 2];
            upd3(s_k1s[tid*2+1], a1, a2, a3);
            upd3(s_k2s[tid*2+1], a1, a2, a3);
            upd3(s_k3s[tid*2+1], a1, a2, a3);
            float f1 = __uint_as_float(a1 & 0xFFFFFE00u);
            float f2 = __uint_as_float(a2 & 0xFFFFFE00u);
            float f3 = __uint_as_float(a3 & 0xFFFFFE00u);
            float px = s_px[tid] + s_px[128 + tid]
                     + s_px[256 + tid] + s_px[384 + tid];
            float gridw = (px < 63.7f) ? 1.7e-5f : (px < 127.7f ? 3.3e-5f : 6.6e-5f);
            float W = gridw + 3.3e-5f + 2.6f * sqrtf(px) * El;
            if (f2 - f1 >= W) {
                s_bkf[tid] = (int)(a1 & 511u); s_flag[tid] = 0;
            } else {
                s_flag[tid] = 1;
                if (f3 - f1 < W) {          // 3+ candidates -> full scan
                    int i = atomicAdd(&g_cnt_full, 1);
                    g_wl_full[i] = base + tid;
                } else {                    // exactly 2 candidates
                    int i = atomicAdd(&g_cnt_pair, 1);
                    g_wl_pair[i]  = base + tid;
                    g_wl_pairk[i] = (int)((a1 & 511u) | ((a2 & 511u) << 16));
                }
            }
        }
        __syncthreads();

        // ---- output + loss for winners ----
        float lsum = 0.f;
        if (!s_flag[p]) {
            const int bestk = s_bkf[p];
            const float4* e4 = (const float4*)(cb + bestk * D_);
            float* op = out + (size_t)b * D_ * HW_ + hw0 + p;
            #pragma unroll
            for (int j4 = 0; j4 < 4; j4++) {
                float4 e = __ldg(e4 + q4 * 4 + j4);
                #pragma unroll
                for (int u = 0; u < 4; u++) {
                    int c = q4 * 16 + 4 * j4 + u;
                    float qq = (u == 0) ? e.x : (u == 1) ? e.y : (u == 2) ? e.z : e.w;
                    float zv = __ldg(zb + (size_t)c * HW_ + p);
                    float dd = __fadd_rn(qq, -zv);
                    lsum = __fmaf_rn(dd, dd, lsum);
                    op[(size_t)c * HW_] = __fadd_rn(zv, dd);
                }
            }
        }
        #pragma unroll
        for (int off = 16; off > 0; off >>= 1)
            lsum += __shfl_down_sync(0xffffffffu, lsum, off);
        if (lane == 0) s_red[wid] = lsum;
        __syncthreads();
        if (tid == 0) {
            float v = 0.f;
            #pragma unroll
            for (int i = 0; i < 16; i++) v += s_red[i];
            atomicAdd(&g_loss_accum, (double)v);
        }
        __syncthreads();
    }
}

// ---------------- fallback: full scans (warp/point) + pairs (thread/point) ----------------
#define FB_CTAS 148
#define FB_TPB  256
__global__ __launch_bounds__(FB_TPB, 1)
void vq_fallback_kernel(const float* __restrict__ z,
                        const float* __restrict__ cb,
                        float* __restrict__ out) {
    extern __shared__ float fsm[];
    float* s_cb = fsm;               // [512][65] padded fp32
    float* s_ye = fsm + K_ * 65;     // exact y

    const int tid  = threadIdx.x;
    const int lane = tid & 31;

    // stage padded codebook + exact y
    for (int idx = tid; idx < K_ * D_; idx += FB_TPB) {
        int k = idx >> 6, i = idx & 63;
        s_cb[k * 65 + i] = __ldg(cb + idx);
    }
    for (int i = tid; i < K_; i += FB_TPB) s_ye[i] = g_y[i];
    __syncthreads();

    float ls_tot = 0.f;

    // ---- phase 1: full scans, one point per WARP, codes strided across lanes ----
    {
        const int gw = (blockIdx.x * FB_TPB + tid) >> 5;
        const int nw = (FB_CTAS * FB_TPB) >> 5;
        const int cnt = g_cnt_full;
        for (int w = gw; w < cnt; w += nw) {
            const int n  = g_wl_full[w];
            const int b  = n >> 12;
            const int hw = n & (HW_ - 1);
            const float* zp = z + (size_t)b * D_ * HW_ + hw;

            float zv[D_];
            #pragma unroll
            for (int i = 0; i < D_; i++) zv[i] = __ldg(zp + (size_t)i * HW_);
            float x = 0.f;
            #pragma unroll
            for (int i = 0; i < D_; i++) x = __fadd_rn(x, __fmul_rn(zv[i], zv[i]));

            // lane handles codes lane + 32*j (conflict-free smem banks), 4-ILP
            float bd = 3.4e38f; int bk = K_;
            #pragma unroll 1
            for (int j4 = 0; j4 < 4; j4++) {
                const int kbase = lane + j4 * 128;
                const float* r0 = s_cb + (kbase +  0) * 65;
                const float* r1 = s_cb + (kbase + 32) * 65;
                const float* r2 = s_cb + (kbase + 64) * 65;
                const float* r3 = s_cb + (kbase + 96) * 65;
                float a0 = 0.f, a1 = 0.f, a2 = 0.f, a3 = 0.f;
                #pragma unroll
                for (int i = 0; i < D_; i++) {
                    float zi = zv[i];
                    a0 = __fmaf_rn(zi, r0[i], a0);
                    a1 = __fmaf_rn(zi, r1[i], a1);
                    a2 = __fmaf_rn(zi, r2[i], a2);
                    a3 = __fmaf_rn(zi, r3[i], a3);
                }
                float d0 = __fadd_rn(__fadd_rn(x, s_ye[kbase +  0]), -__fmul_rn(2.f, a0));
                float d1 = __fadd_rn(__fadd_rn(x, s_ye[kbase + 32]), -__fmul_rn(2.f, a1));
                float d2 = __fadd_rn(__fadd_rn(x, s_ye[kbase + 64]), -__fmul_rn(2.f, a2));
                float d3 = __fadd_rn(__fadd_rn(x, s_ye[kbase + 96]), -__fmul_rn(2.f, a3));
                if (d0 < bd || (d0 == bd && kbase      < bk)) { bd = d0; bk = kbase; }
                if (d1 < bd || (d1 == bd && kbase + 32 < bk)) { bd = d1; bk = kbase + 32; }
                if (d2 < bd || (d2 == bd && kbase + 64 < bk)) { bd = d2; bk = kbase + 64; }
                if (d3 < bd || (d3 == bd && kbase + 96 < bk)) { bd = d3; bk = kbase + 96; }
            }
            // lexicographic (d, k) min across lanes => first-index tie rule
            #pragma unroll
            for (int off = 16; off > 0; off >>= 1) {
                float od = __shfl_down_sync(0xffffffffu, bd, off);
                int   ok = __shfl_down_sync(0xffffffffu, bk, off);
                if (od < bd || (od == bd && ok < bk)) { bd = od; bk = ok; }
            }
            bk = __shfl_sync(0xffffffffu, bk, 0);

            float* op = out + (size_t)b * D_ * HW_ + hw;
            const float* e = s_cb + bk * 65;
            #pragma unroll
            for (int h = 0; h < 2; h++) {
                int c = lane + 32 * h;
                float dd = __fadd_rn(e[c], -zv[c]);
                ls_tot = __fmaf_rn(dd, dd, ls_tot);
                op[(size_t)c * HW_] = __fadd_rn(zv[c], dd);
            }
        }
    }

    // ---- phase 2: pairs, one point per THREAD (128 FMA each) ----
    {
        const int cnt = g_cnt_pair;
        for (int idx = blockIdx.x * FB_TPB + tid; idx < cnt;
             idx += FB_CTAS * FB_TPB) {
            const int n  = g_wl_pair[idx];
            const int kk = g_wl_pairk[idx];
            const int k1 = kk & 0xFFFF, k2 = kk >> 16;
            const int b  = n >> 12;
            const int hw = n & (HW_ - 1);
            const float* zp = z + (size_t)b * D_ * HW_ + hw;
            const float* e1r = s_cb + k1 * 65;
            const float* e2r = s_cb + k2 * 65;

            float zv[D_];
            float x = 0.f, m1 = 0.f, m2 = 0.f;
            #pragma unroll
            for (int i = 0; i < D_; i++) {
                float zi = __ldg(zp + (size_t)i * HW_);
                zv[i] = zi;
                x  = __fadd_rn(x, __fmul_rn(zi, zi));
                m1 = __fmaf_rn(zi, e1r[i], m1);
                m2 = __fmaf_rn(zi, e2r[i], m2);
            }
            float d1 = __fadd_rn(__fadd_rn(x, s_ye[k1]), -__fmul_rn(2.f, m1));
            float d2 = __fadd_rn(__fadd_rn(x, s_ye[k2]), -__fmul_rn(2.f, m2));
            int bk;
            if (d1 < d2 || (d1 == d2 && k1 < k2)) bk = k1; else bk = k2;

            float* op = out + (size_t)b * D_ * HW_ + hw;
            const float* e = s_cb + bk * 65;
            #pragma unroll
            for (int i = 0; i < D_; i++) {
                float dd = __fadd_rn(e[i], -zv[i]);
                ls_tot = __fmaf_rn(dd, dd, ls_tot);
                op[(size_t)i * HW_] = __fadd_rn(zv[i], dd);
            }
        }
    }

    #pragma unroll
    for (int off = 16; off > 0; off >>= 1)
        ls_tot += __shfl_down_sync(0xffffffffu, ls_tot, off);
    if (lane == 0 && ls_tot != 0.f)
        atomicAdd(&g_loss_accum, (double)ls_tot);
}

// ---------------- finalize: write loss, reset state for graph replays ----------------
__global__ void vq_finalize_kernel(float* __restrict__ out, int loss_idx) {
    out[loss_idx] = (float)(g_loss_accum * 1.25 / (double)NELEM);
    g_loss_accum = 0.0;
    g_cnt_full = 0;
    g_cnt_pair = 0;
}

extern "C" void kernel_launch(void* const* d_in, const int* in_sizes, int n_in,
                              void* d_out, int out_size) {
    const float* z  = (const float*)d_in[0];
    const float* cb = (const float*)d_in[1];
    float* out = (float*)d_out;

    static bool attr_set = false;
    if (!attr_set) {
        cudaFuncSetAttribute(vq_main_kernel,
                             cudaFuncAttributeMaxDynamicSharedMemorySize,
                             SMEM_TOTAL);
        cudaFuncSetAttribute(vq_fallback_kernel,
                             cudaFuncAttributeMaxDynamicSharedMemorySize,
                             FB_SMEM);
        attr_set = true;
    }

    vq_main_kernel<<<MGRID, MTPB, SMEM_TOTAL>>>(z, cb, out);
    vq_fallback_kernel<<<FB_CTAS, FB_TPB, FB_SMEM>>>(z, cb, out);
    vq_finalize_kernel<<<1, 1>>>(out, out_size - 1);
}

// round 14
// speedup vs baseline: 22.8385x; 1.3576x over previous
#include <cuda_runtime.h>
#include <cuda_fp16.h>
#include <cstdint>

// ---------------- problem constants ----------------
#define D_    64
#define HW_   4096
#define K_    512
#define NPTS  131072
#define NELEM 8388608LL

#define MTPB   512
#define MGRID  148
#define NTILES (NPTS / 128)   // 1024

// ---- main smem byte offsets (A/B tiles 1024-aligned for SW128) ----
#define SM_Y     0        // 512 f32 (y + 0.5, screen)
#define SM_YE    2048     // 512 f32 (exact y)
#define SM_BKF   4096     // 128 int
#define SM_FLAG  4608     // 128 int
#define SM_RED   5120     // 32 f32
#define SM_K1S   5248     // 256 u32
#define SM_K2S   6272     // 256 u32
#define SM_K3S   7296     // 256 u32
#define SM_PX    8320     // 4*128 f32
#define SM_BMAX  10368    // 2 f32 (El, Bmax)
#define SM_AHI   12288    // 128*128 B fp16 z (SW128)
#define SM_BH    28672    // 512*128 B fp16 cb (SW128)
#define SMEM_TOTAL 94208

// fallback smem: padded fp32 codebook [512][65] + exact y
#define FB_SMEM (K_ * 65 * 4 + K_ * 4)   // 135168 B
#define FB_CTAS 148
#define FB_TPB  256

// ---------------- device globals (zero-init; fallback resets) ----------------
__device__ double g_loss_accum;
__device__ int    g_cnt_full;
__device__ int    g_done;
__device__ int    g_wl_full[NPTS];
__device__ float  g_y[K_];            // EXACT sequential sum e_i^2

#define SWZ128(off) ((off) ^ (((off) >> 3) & 0x70))

__device__ __forceinline__ uint32_t smem_u32_of(const void* p) {
    uint32_t a;
    asm("{ .reg .u64 t; cvta.to.shared.u64 t, %1; cvt.u32.u64 %0, t; }"
        : "=r"(a) : "l"(p));
    return a;
}
__device__ __forceinline__ void mma_f16(float* c, const uint32_t* a,
                                        uint32_t b0, uint32_t b1) {
    asm volatile(
        "mma.sync.aligned.m16n8k16.row.col.f32.f16.f16.f32 "
        "{%0,%1,%2,%3}, {%4,%5,%6,%7}, {%8,%9}, {%0,%1,%2,%3};"
        : "+f"(c[0]), "+f"(c[1]), "+f"(c[2]), "+f"(c[3])
        : "r"(a[0]), "r"(a[1]), "r"(a[2]), "r"(a[3]), "r"(b0), "r"(b1));
}
__device__ __forceinline__ void ldsm_x4(uint32_t* r, uint32_t addr) {
    asm volatile(
        "ldmatrix.sync.aligned.m8n8.x4.shared.b16 {%0,%1,%2,%3}, [%4];"
        : "=r"(r[0]), "=r"(r[1]), "=r"(r[2]), "=r"(r[3]) : "r"(addr));
}
__device__ __forceinline__ uint32_t pack_f16x2(float lo, float hi) {
    __half2 h = __floats2half2_rn(lo, hi);
    return *reinterpret_cast<uint32_t*>(&h);
}
// key = (fbits(t) & ~0x1FF) | k ; t > 0 -> monotone; ties -> smaller k.
__device__ __forceinline__ uint32_t mkkey(float t, int k) {
    return (__float_as_uint(t) & 0xFFFFFE00u) | (uint32_t)k;
}
// Insert key into sorted top-3 (branchless).
__device__ __forceinline__ void upd3(uint32_t key, uint32_t& k1,
                                     uint32_t& k2, uint32_t& k3) {
    k3 = min(k3, max(k2, key));
    k2 = min(k2, max(k1, key));
    k1 = min(k1, key);
}

// ---------------- main: persistent, 1-pass fp16 screen + 3-tier ----------------
__global__ __launch_bounds__(MTPB, 1)
void vq_main_kernel(const float* __restrict__ z,
                    const float* __restrict__ cb,
                    float* __restrict__ out) {
    extern __shared__ char smem[];
    const uint32_t smb = smem_u32_of(smem);
    float*    s_y    = (float*)(smem + SM_Y);
    float*    s_ye   = (float*)(smem + SM_YE);
    int*      s_bkf  = (int*)(smem + SM_BKF);
    int*      s_flag = (int*)(smem + SM_FLAG);
    float*    s_red  = (float*)(smem + SM_RED);
    uint32_t* s_k1s  = (uint32_t*)(smem + SM_K1S);
    uint32_t* s_k2s  = (uint32_t*)(smem + SM_K2S);
    uint32_t* s_k3s  = (uint32_t*)(smem + SM_K3S);
    float*    s_px   = (float*)(smem + SM_PX);
    float*    s_bmax = (float*)(smem + SM_BMAX);

    const int tid  = threadIdx.x;
    const int wid  = tid >> 5;
    const int lane = tid & 31;
    const int g    = lane >> 2;
    const int tg   = lane & 3;
    const int p    = tid & 127;
    const int q4   = tid >> 7;

    // ---- stage B once: exact y; fp16 tile; exact max ||e-fp16(e)||, max ||e|| ----
    {
        const int k = tid;        // 0..511
        const float4* e4 = (const float4*)(cb + k * D_);
        float ev[D_];
        #pragma unroll
        for (int i = 0; i < 16; i++) {
            float4 v = __ldg(e4 + i);
            ev[4*i] = v.x; ev[4*i+1] = v.y; ev[4*i+2] = v.z; ev[4*i+3] = v.w;
        }
        float s = 0.f;
        #pragma unroll
        for (int i = 0; i < D_; i++) s = __fadd_rn(s, __fmul_rn(ev[i], ev[i]));
        if (blockIdx.x == 0) g_y[k] = s;
        s_ye[k] = s;
        s_y[k]  = s + 0.5f;
        float elsq = 0.f;
        #pragma unroll
        for (int j = 0; j < 32; j++) {
            float v0 = ev[2*j], v1 = ev[2*j+1];
            float h0 = __half2float(__float2half_rn(v0));
            float h1 = __half2float(__float2half_rn(v1));
            float l0 = v0 - h0, l1 = v1 - h1;
            elsq = fmaf(l0, l0, fmaf(l1, l1, elsq));
            uint32_t off = (uint32_t)(k * 128 + j * 4);
            *(uint32_t*)(smem + SM_BH + SWZ128(off)) = pack_f16x2(v0, v1);
        }
        float ymax = s;
        #pragma unroll
        for (int off = 16; off > 0; off >>= 1) {
            elsq = fmaxf(elsq, __shfl_xor_sync(0xffffffffu, elsq, off));
            ymax = fmaxf(ymax, __shfl_xor_sync(0xffffffffu, ymax, off));
        }
        if (lane == 0) { s_red[wid] = elsq; s_red[16 + wid] = ymax; }
    }
    __syncthreads();
    if (tid == 0) {
        float m = 0.f, ym = 0.f;
        #pragma unroll
        for (int i = 0; i < 16; i++) {
            m  = fmaxf(m,  s_red[i]);
            ym = fmaxf(ym, s_red[16 + i]);
        }
        s_bmax[0] = sqrtf(m) * 1.001f;    // El
        s_bmax[1] = sqrtf(ym) * 1.001f;   // Bmax = max ||e||
    }
    __syncthreads();
    // per-point window factor: 2.2 * (El + 2^-11 * Bmax)
    const float Wfac = 2.2f * (s_bmax[0] + 4.8828125e-4f * s_bmax[1]);

    const int row0 = (wid >> 1) * 16 + g;
    const int nh   = wid & 1;
    const int lr = lane & 7;
    const int ms = lane >> 3;
    const uint32_t colx0 = (uint32_t)((ms * 16) ^ (lr << 4));
    const uint32_t colx1 = (uint32_t)((64 + ms * 16) ^ (lr << 4));
    const uint32_t browz = (uint32_t)((nh * 256 + lr) * 128);

    for (int tile = blockIdx.x; tile < NTILES; tile += gridDim.x) {
        const int base = tile * 128;
        const int b    = base >> 12;
        const int hw0  = base & (HW_ - 1);
        const float* zb = z + (size_t)b * D_ * HW_ + hw0;

        // ---- stage A: z -> fp16 tile only; ||z||^2 partials ----
        {
            const int c0s = q4 * 16;
            float px = 0.f;
            #pragma unroll
            for (int j = 0; j < 8; j++) {
                int c = c0s + 2 * j;
                float v0 = __ldg(zb + (size_t)c * HW_ + p);
                float v1 = __ldg(zb + (size_t)(c + 1) * HW_ + p);
                px = fmaf(v0, v0, fmaf(v1, v1, px));
                uint32_t off = (uint32_t)(p * 128 + c * 2);
                *(uint32_t*)(smem + SM_AHI + SWZ128(off)) = pack_f16x2(v0, v1);
            }
            s_px[q4 * 128 + p] = px;
        }
        __syncthreads();

        // ---- A fragments (validated layout) ----
        uint32_t ah[4][4];
        #pragma unroll
        for (int ks = 0; ks < 4; ks++) {
            uint32_t o = (uint32_t)(row0 * 128 + ks * 32 + tg * 4);
            ah[ks][0] = *(uint32_t*)(smem + SM_AHI + SWZ128(o));
            ah[ks][1] = *(uint32_t*)(smem + SM_AHI + SWZ128(o + 8 * 128));
            ah[ks][2] = *(uint32_t*)(smem + SM_AHI + SWZ128(o + 16));
            ah[ks][3] = *(uint32_t*)(smem + SM_AHI + SWZ128(o + 8 * 128 + 16));
        }

        uint32_t bh0 = smb + SM_BH + browz + colx0;
        uint32_t bh1 = smb + SM_BH + browz + colx1;

        uint32_t k1a = 0xFFFFFFFFu, k2a = 0xFFFFFFFFu, k3a = 0xFFFFFFFFu;
        uint32_t k1b = 0xFFFFFFFFu, k2b = 0xFFFFFFFFu, k3b = 0xFFFFFFFFu;

        #pragma unroll 4
        for (int nb = 0; nb < 32; nb++) {
            uint32_t h1[4], h2[4];
            ldsm_x4(h1, bh0); ldsm_x4(h2, bh1);
            bh0 += 1024; bh1 += 1024;

            float acc[4] = {0.f, 0.f, 0.f, 0.f};
            mma_f16(acc, ah[0], h1[0], h1[1]);
            mma_f16(acc, ah[1], h1[2], h1[3]);
            mma_f16(acc, ah[2], h2[0], h2[1]);
            mma_f16(acc, ah[3], h2[2], h2[3]);

            const int c0 = nh * 256 + nb * 8 + tg * 2;
            float2 y2 = *(const float2*)&s_y[c0];       // y + 0.5
            float t0 = fmaf(-2.f, acc[0], y2.x);        // > 0
            float t1 = fmaf(-2.f, acc[1], y2.y);
            float t2 = fmaf(-2.f, acc[2], y2.x);
            float t3 = fmaf(-2.f, acc[3], y2.y);
            upd3(mkkey(t0, c0),     k1a, k2a, k3a);
            upd3(mkkey(t1, c0 + 1), k1a, k2a, k3a);
            upd3(mkkey(t2, c0),     k1b, k2b, k3b);
            upd3(mkkey(t3, c0 + 1), k1b, k2b, k3b);
        }

        // quad merge (tg bits): top-3 on u32 keys
        #pragma unroll
        for (int off = 1; off <= 2; off <<= 1) {
            uint32_t n1 = __shfl_xor_sync(0xffffffffu, k1a, off);
            uint32_t n2 = __shfl_xor_sync(0xffffffffu, k2a, off);
            uint32_t n3 = __shfl_xor_sync(0xffffffffu, k3a, off);
            upd3(n1, k1a, k2a, k3a); upd3(n2, k1a, k2a, k3a);
            upd3(n3, k1a, k2a, k3a);
            n1 = __shfl_xor_sync(0xffffffffu, k1b, off);
            n2 = __shfl_xor_sync(0xffffffffu, k2b, off);
            n3 = __shfl_xor_sync(0xffffffffu, k3b, off);
            upd3(n1, k1b, k2b, k3b); upd3(n2, k1b, k2b, k3b);
            upd3(n3, k1b, k2b, k3b);
        }
        if (tg == 0) {
            s_k1s[row0 * 2 + nh] = k1a; s_k2s[row0 * 2 + nh] = k2a;
            s_k3s[row0 * 2 + nh] = k3a;
            s_k1s[(row0 + 8) * 2 + nh] = k1b; s_k2s[(row0 + 8) * 2 + nh] = k2b;
            s_k3s[(row0 + 8) * 2 + nh] = k3b;
        }
        __syncthreads();

        // ---- decision: merge halves; winner / inline-pair / full worklist ----
        if (tid < 128) {
            uint32_t a1 = s_k1s[tid * 2], a2 = s_k2s[tid * 2], a3 = s_k3s[tid * 2];
            upd3(s_k1s[tid*2+1], a1, a2, a3);
            upd3(s_k2s[tid*2+1], a1, a2, a3);
            upd3(s_k3s[tid*2+1], a1, a2, a3);
            float f1 = __uint_as_float(a1 & 0xFFFFFE00u);
            float f2 = __uint_as_float(a2 & 0xFFFFFE00u);
            float f3 = __uint_as_float(a3 & 0xFFFFFE00u);
            float px = s_px[tid] + s_px[128 + tid]
                     + s_px[256 + tid] + s_px[384 + tid];
            float gridw = (px < 63.7f) ? 1.7e-5f : (px < 127.7f ? 3.3e-5f : 6.6e-5f);
            float W = gridw + 4.4e-5f + Wfac * sqrtf(px);
            if (f2 - f1 >= W) {
                s_bkf[tid] = (int)(a1 & 511u); s_flag[tid] = 0;
            } else if (f3 - f1 >= W) {
                // exactly 2 candidates: resolve inline, bit-exact
                const int c1 = (int)(a1 & 511u), c2 = (int)(a2 & 511u);
                const float4* e1r = (const float4*)(cb + c1 * D_);
                const float4* e2r = (const float4*)(cb + c2 * D_);
                float x = 0.f, m1 = 0.f, m2 = 0.f;
                #pragma unroll
                for (int i = 0; i < 16; i++) {
                    float z0 = __ldg(zb + (size_t)(4*i+0) * HW_ + tid);
                    float z1 = __ldg(zb + (size_t)(4*i+1) * HW_ + tid);
                    float z2 = __ldg(zb + (size_t)(4*i+2) * HW_ + tid);
                    float z3 = __ldg(zb + (size_t)(4*i+3) * HW_ + tid);
                    float4 e1 = __ldg(e1r + i);
                    float4 e2 = __ldg(e2r + i);
                    x = __fadd_rn(x, __fmul_rn(z0, z0));
                    x = __fadd_rn(x, __fmul_rn(z1, z1));
                    x = __fadd_rn(x, __fmul_rn(z2, z2));
                    x = __fadd_rn(x, __fmul_rn(z3, z3));
                    m1 = __fmaf_rn(z0, e1.x, m1); m2 = __fmaf_rn(z0, e2.x, m2);
                    m1 = __fmaf_rn(z1, e1.y, m1); m2 = __fmaf_rn(z1, e2.y, m2);
                    m1 = __fmaf_rn(z2, e1.z, m1); m2 = __fmaf_rn(z2, e2.z, m2);
                    m1 = __fmaf_rn(z3, e1.w, m1); m2 = __fmaf_rn(z3, e2.w, m2);
                }
                float d1 = __fadd_rn(__fadd_rn(x, s_ye[c1]), -__fmul_rn(2.f, m1));
                float d2 = __fadd_rn(__fadd_rn(x, s_ye[c2]), -__fmul_rn(2.f, m2));
                int bk = (d1 < d2 || (d1 == d2 && c1 < c2)) ? c1 : c2;
                s_bkf[tid] = bk; s_flag[tid] = 0;
            } else {
                s_flag[tid] = 1;
                int i = atomicAdd(&g_cnt_full, 1);
                g_wl_full[i] = base + tid;
            }
        }
        __syncthreads();

        // ---- output + loss for resolved points ----
        float lsum = 0.f;
        if (!s_flag[p]) {
            const int bestk = s_bkf[p];
            const float4* e4 = (const float4*)(cb + bestk * D_);
            float* op = out + (size_t)b * D_ * HW_ + hw0 + p;
            #pragma unroll
            for (int j4 = 0; j4 < 4; j4++) {
                float4 e = __ldg(e4 + q4 * 4 + j4);
                #pragma unroll
                for (int u = 0; u < 4; u++) {
                    int c = q4 * 16 + 4 * j4 + u;
                    float qq = (u == 0) ? e.x : (u == 1) ? e.y : (u == 2) ? e.z : e.w;
                    float zv = __ldg(zb + (size_t)c * HW_ + p);
                    float dd = __fadd_rn(qq, -zv);
                    lsum = __fmaf_rn(dd, dd, lsum);
                    op[(size_t)c * HW_] = __fadd_rn(zv, dd);
                }
            }
        }
        #pragma unroll
        for (int off = 16; off > 0; off >>= 1)
            lsum += __shfl_down_sync(0xffffffffu, lsum, off);
        if (lane == 0) s_red[wid] = lsum;
        __syncthreads();
        if (tid == 0) {
            float v = 0.f;
            #pragma unroll
            for (int i = 0; i < 16; i++) v += s_red[i];
            atomicAdd(&g_loss_accum, (double)v);
        }
        __syncthreads();
    }
}

// ---------------- fallback: full-tier scans + fused finalize ----------------
__global__ __launch_bounds__(FB_TPB, 1)
void vq_fallback_kernel(const float* __restrict__ z,
                        const float* __restrict__ cb,
                        float* __restrict__ out, int loss_idx) {
    extern __shared__ float fsm[];
    float* s_cb = fsm;               // [512][65] padded fp32
    float* s_ye = fsm + K_ * 65;     // exact y

    const int tid  = threadIdx.x;
    const int lane = tid & 31;
    const int cnt  = g_cnt_full;

    if (cnt > 0) {
        // stage padded codebook + exact y
        for (int idx = tid; idx < K_ * D_; idx += FB_TPB) {
            int k = idx >> 6, i = idx & 63;
            s_cb[k * 65 + i] = __ldg(cb + idx);
        }
        for (int i = tid; i < K_; i += FB_TPB) s_ye[i] = g_y[i];
        __syncthreads();

        float ls_tot = 0.f;
        const int gw = (blockIdx.x * FB_TPB + tid) >> 5;
        const int nw = (FB_CTAS * FB_TPB) >> 5;
        for (int w = gw; w < cnt; w += nw) {
            const int n  = g_wl_full[w];
            const int b  = n >> 12;
            const int hw = n & (HW_ - 1);
            const float* zp = z + (size_t)b * D_ * HW_ + hw;

            float zv[D_];
            #pragma unroll
            for (int i = 0; i < D_; i++) zv[i] = __ldg(zp + (size_t)i * HW_);
            float x = 0.f;
            #pragma unroll
            for (int i = 0; i < D_; i++) x = __fadd_rn(x, __fmul_rn(zv[i], zv[i]));

            // lane handles codes lane + 32*j (conflict-free banks), 4-ILP
            float bd = 3.4e38f; int bk = K_;
            #pragma unroll 1
            for (int j4 = 0; j4 < 4; j4++) {
                const int kbase = lane + j4 * 128;
                const float* r0 = s_cb + (kbase +  0) * 65;
                const float* r1 = s_cb + (kbase + 32) * 65;
                const float* r2 = s_cb + (kbase + 64) * 65;
                const float* r3 = s_cb + (kbase + 96) * 65;
                float a0 = 0.f, a1 = 0.f, a2 = 0.f, a3 = 0.f;
                #pragma unroll
                for (int i = 0; i < D_; i++) {
                    float zi = zv[i];
                    a0 = __fmaf_rn(zi, r0[i], a0);
                    a1 = __fmaf_rn(zi, r1[i], a1);
                    a2 = __fmaf_rn(zi, r2[i], a2);
                    a3 = __fmaf_rn(zi, r3[i], a3);
                }
                float d0 = __fadd_rn(__fadd_rn(x, s_ye[kbase +  0]), -__fmul_rn(2.f, a0));
                float d1 = __fadd_rn(__fadd_rn(x, s_ye[kbase + 32]), -__fmul_rn(2.f, a1));
                float d2 = __fadd_rn(__fadd_rn(x, s_ye[kbase + 64]), -__fmul_rn(2.f, a2));
                float d3 = __fadd_rn(__fadd_rn(x, s_ye[kbase + 96]), -__fmul_rn(2.f, a3));
                if (d0 < bd || (d0 == bd && kbase      < bk)) { bd = d0; bk = kbase; }
                if (d1 < bd || (d1 == bd && kbase + 32 < bk)) { bd = d1; bk = kbase + 32; }
                if (d2 < bd || (d2 == bd && kbase + 64 < bk)) { bd = d2; bk = kbase + 64; }
                if (d3 < bd || (d3 == bd && kbase + 96 < bk)) { bd = d3; bk = kbase + 96; }
            }
            // lexicographic (d, k) min across lanes => first-index tie rule
            #pragma unroll
            for (int off = 16; off > 0; off >>= 1) {
                float od = __shfl_down_sync(0xffffffffu, bd, off);
                int   ok = __shfl_down_sync(0xffffffffu, bk, off);
                if (od < bd || (od == bd && ok < bk)) { bd = od; bk = ok; }
            }
            bk = __shfl_sync(0xffffffffu, bk, 0);

            float* op = out + (size_t)b * D_ * HW_ + hw;
            const float* e = s_cb + bk * 65;
            #pragma unroll
            for (int h = 0; h < 2; h++) {
                int c = lane + 32 * h;
                float dd = __fadd_rn(e[c], -zv[c]);
                ls_tot = __fmaf_rn(dd, dd, ls_tot);
                op[(size_t)c * HW_] = __fadd_rn(zv[c], dd);
            }
        }
        #pragma unroll
        for (int off = 16; off > 0; off >>= 1)
            ls_tot += __shfl_down_sync(0xffffffffu, ls_tot, off);
        if (lane == 0 && ls_tot != 0.f)
            atomicAdd(&g_loss_accum, (double)ls_tot);
    }

    // fused finalize: last CTA writes loss + resets state for graph replays
    __syncthreads();
    if (tid == 0) {
        __threadfence();
        int old = atomicAdd(&g_done, 1);
        if (old == FB_CTAS - 1) {
            double lv = atomicAdd(&g_loss_accum, 0.0);
            out[loss_idx] = (float)(lv * 1.25 / (double)NELEM);
            g_loss_accum = 0.0;
            g_cnt_full = 0;
            g_done = 0;
            __threadfence();
        }
    }
}

extern "C" void kernel_launch(void* const* d_in, const int* in_sizes, int n_in,
                              void* d_out, int out_size) {
    const float* z  = (const float*)d_in[0];
    const float* cb = (const float*)d_in[1];
    float* out = (float*)d_out;

    static bool attr_set = false;
    if (!attr_set) {
        cudaFuncSetAttribute(vq_main_kernel,
                             cudaFuncAttributeMaxDynamicSharedMemorySize,
                             SMEM_TOTAL);
        cudaFuncSetAttribute(vq_fallback_kernel,
                             cudaFuncAttributeMaxDynamicSharedMemorySize,
                             FB_SMEM);
        attr_set = true;
    }

    vq_main_kernel<<<MGRID, MTPB, SMEM_TOTAL>>>(z, cb, out);
    vq_fallback_kernel<<<FB_CTAS, FB_TPB, FB_SMEM>>>(z, cb, out, out_size - 1);
}